// round 14
// baseline (speedup 1.0000x reference)
#include <cuda_runtime.h>
#include <cuda_fp16.h>
#include <cstdint>
#include <math.h>

#define Nn 20000
#define Ee 500000

// ---------------- scratch (device globals; no allocation) ----------------
// g_deg / g_cnt are zeroed at the END of each call (cleanup in k_final);
// first call relies on static zero-init of __device__ globals.
__device__ float g_deg[Nn];
__device__ int   g_cnt[Nn];
__device__ float g_dinv[Nn];
__device__ int   g_off[Nn + 1];
__device__ int   g_pos[Nn];
__device__ uint2 g_csr[Ee];      // interleaved (row, half2(w,w) bits)
__device__ float g_bufA[Nn * 512];
__device__ float g_bufB[Nn * 512];
__device__ float g_wT[344064];   // holds 344064 halves (transposed fp16 weights)
__device__ float g_Z[128 * 128];

// ---------------- fused setup: x cast, W transpose, deg/cnt atomics, Z zero ----------------
__global__ void k_setup(const float* __restrict__ x,
                        const float* __restrict__ W1, const float* __restrict__ W2,
                        const float* __restrict__ W3, const float* __restrict__ W4,
                        const float* __restrict__ W5,
                        const int* __restrict__ col, const float* __restrict__ ew,
                        __half* __restrict__ WTh, __half* __restrict__ xh) {
    int i = blockIdx.x * blockDim.x + threadIdx.x;
    if (i < 640000) {  // Nn*32 float4 units: cast x -> fp16
        float4 v = ((const float4*)x)[i];
        __half2 h0 = __floats2half2_rn(v.x, v.y);
        __half2 h1 = __floats2half2_rn(v.z, v.w);
        uint2 o;
        o.x = *(uint32_t*)&h0;
        o.y = *(uint32_t*)&h1;
        ((uint2*)xh)[i] = o;
    } else if (i < 984064) {  // transpose W[K,N] -> Wt[N,K] fp16
        int j = i - 640000;
        if (j < 32768) {
            int k = j >> 8, n = j & 255;
            WTh[n * 128 + k] = __float2half_rn(W1[j]);
        } else if (j < 163840) {
            int q = j - 32768;
            int k = q >> 9, n = q & 511;
            WTh[32768 + n * 256 + k] = __float2half_rn(W2[q]);
        } else if (j < 294912) {
            int q = j - 163840;
            int k = q >> 8, n = q & 255;
            WTh[163840 + n * 512 + k] = __float2half_rn(W3[q]);
        } else if (j < 327680) {
            int q = j - 294912;
            int k = q >> 7, n = q & 127;
            WTh[294912 + n * 256 + k] = __float2half_rn(W4[q]);
        } else {
            int q = j - 327680;
            int k = q >> 7, n = q & 127;
            WTh[327680 + n * 128 + k] = __float2half_rn(W5[q]);
        }
    } else if (i < 1484064) {  // degree + count atomics (deg/cnt pre-zeroed by cleanup)
        int j = i - 984064;
        int c = col[j];
        atomicAdd(&g_deg[c], ew[j]);
        atomicAdd(&g_cnt[c], 1);
    } else if (i < 1500448) {  // zero Z (written only by k_hth, much later)
        g_Z[i - 1484064] = 0.f;
    }
}

// scan of g_cnt -> g_off/g_pos, plus dinv (merged; 1 block, 1024 threads)
__global__ void __launch_bounds__(1024) k_scan() {
    __shared__ int wsum[32];
    int t = threadIdx.x;
    const int C = 20;
    int base = t * C;
    int cnt[C];
    int s = 0;
#pragma unroll
    for (int i = 0; i < C; i++) {
        int idx = base + i;
        int c = 0;
        if (idx < Nn) {
            c = g_cnt[idx];
            g_dinv[idx] = rsqrtf(g_deg[idx] + 1.0f);
        }
        cnt[i] = c;
        s += c;
    }
    int lane = t & 31, w = t >> 5;
    int v = s;
#pragma unroll
    for (int o = 1; o < 32; o <<= 1) {
        int u = __shfl_up_sync(0xFFFFFFFF, v, o);
        if (lane >= o) v += u;
    }
    if (lane == 31) wsum[w] = v;
    __syncthreads();
    if (w == 0) {
        int x = wsum[lane];
#pragma unroll
        for (int o = 1; o < 32; o <<= 1) {
            int u = __shfl_up_sync(0xFFFFFFFF, x, o);
            if (lane >= o) x += u;
        }
        wsum[lane] = x;
    }
    __syncthreads();
    int run = v - s + (w > 0 ? wsum[w - 1] : 0);
#pragma unroll
    for (int i = 0; i < C; i++) {
        int idx = base + i;
        if (idx < Nn) {
            g_off[idx] = run;
            g_pos[idx] = run;
            run += cnt[i];
        }
    }
    if (t == 1023) g_off[Nn] = run;
}

__global__ void k_fill(const int* __restrict__ row, const int* __restrict__ col,
                       const float* __restrict__ w) {
    int i = blockIdx.x * blockDim.x + threadIdx.x;
    if (i >= Ee) return;
    int r = row[i], c = col[i];
    float nw = g_dinv[r] * w[i] * g_dinv[c];
    int p = atomicAdd(&g_pos[c], 1);
    __half2 wh = __floats2half2_rn(nw, nw);
    uint2 pr;
    pr.x = (uint32_t)r;
    pr.y = *(uint32_t*)&wh;
    g_csr[p] = pr;
}

// ---------------- narrow aggregation (128-dim rows): warp per node, uint2 lanes ----------------
#define HACC_EDGE(mm, vv)                                             \
    {                                                                 \
        __half2 w_ = *(__half2*)&(mm).y;                              \
        a0 = __hfma2(w_, *(__half2*)&(vv).x, a0);                     \
        a1 = __hfma2(w_, *(__half2*)&(vv).y, a1);                     \
    }
#define HFLUSH()                                                      \
    {                                                                 \
        float2 f0_ = __half22float2(a0);                              \
        float2 f1_ = __half22float2(a1);                              \
        acc.x += f0_.x; acc.y += f0_.y;                               \
        acc.z += f1_.x; acc.w += f1_.y;                               \
    }

// MODE 0: raw agg; MODE 1: agg + bias + BN + sigmoid
template <int MODE>
__global__ void __launch_bounds__(256) k_agg16(
    const __half* __restrict__ src, __half* __restrict__ dst,
    int total_w,
    const float* __restrict__ b, const float* __restrict__ gm,
    const float* __restrict__ be, const float* __restrict__ mn,
    const float* __restrict__ vr) {
    int wid = (blockIdx.x * 256 + threadIdx.x) >> 5;
    int lane = threadIdx.x & 31;
    if (wid >= total_w) return;
    int node = wid;
    int cw = lane;
    const uint2* s2 = (const uint2*)src;
    const uint2* cp = g_csr;
    const __half2 hz = __floats2half2_rn(0.f, 0.f);

    float s0 = g_dinv[node];
    s0 *= s0;
    uint2 sv = s2[node * 32 + cw];
    float2 p0 = __half22float2(*(__half2*)&sv.x);
    float2 p1 = __half22float2(*(__half2*)&sv.y);
    float4 acc = make_float4(s0 * p0.x, s0 * p0.y, s0 * p1.x, s0 * p1.y);

    int e = g_off[node];
    int e1 = g_off[node + 1];
    for (; e + 8 <= e1; e += 8) {
        uint2 m[8], v[8];
#pragma unroll
        for (int j = 0; j < 8; j++) m[j] = cp[e + j];
#pragma unroll
        for (int j = 0; j < 8; j++) v[j] = s2[m[j].x * 32 + cw];
        __half2 a0 = hz, a1 = hz;
#pragma unroll
        for (int j = 0; j < 8; j++) HACC_EDGE(m[j], v[j]);
        HFLUSH();
    }
    if (e < e1) {
        uint2 m[8], v[8];
#pragma unroll
        for (int j = 0; j < 8; j++) {
            int idx = e + j;
            uint2 mm = make_uint2(0u, 0u);
            if (idx < e1) mm = cp[idx];
            m[j] = mm;
        }
#pragma unroll
        for (int j = 0; j < 8; j++) v[j] = s2[m[j].x * 32 + cw];
        __half2 a0 = hz, a1 = hz;
#pragma unroll
        for (int j = 0; j < 8; j++) HACC_EDGE(m[j], v[j]);
        HFLUSH();
    }

    if (MODE == 1) {
        float4 bv = ((const float4*)b)[cw];
        float4 gv = ((const float4*)gm)[cw];
        float4 bev = ((const float4*)be)[cw];
        float4 mv = ((const float4*)mn)[cw];
        float4 vv = ((const float4*)vr)[cw];
        float sx = gv.x * rsqrtf(vv.x + 1e-3f);
        float sy = gv.y * rsqrtf(vv.y + 1e-3f);
        float sz = gv.z * rsqrtf(vv.z + 1e-3f);
        float sw = gv.w * rsqrtf(vv.w + 1e-3f);
        acc.x = (acc.x + bv.x - mv.x) * sx + bev.x;
        acc.y = (acc.y + bv.y - mv.y) * sy + bev.y;
        acc.z = (acc.z + bv.z - mv.z) * sz + bev.z;
        acc.w = (acc.w + bv.w - mv.w) * sw + bev.w;
        acc.x = 1.f / (1.f + __expf(-acc.x));
        acc.y = 1.f / (1.f + __expf(-acc.y));
        acc.z = 1.f / (1.f + __expf(-acc.z));
        acc.w = 1.f / (1.f + __expf(-acc.w));
    }
    __half2 h0 = __floats2half2_rn(acc.x, acc.y);
    __half2 h1 = __floats2half2_rn(acc.z, acc.w);
    uint2 o;
    o.x = *(uint32_t*)&h0;
    o.y = *(uint32_t*)&h1;
    ((uint2*)dst)[node * 32 + cw] = o;
}

// ---------------- wide aggregation (256-dim rows): warp per node, uint4 lanes ----------------
// Lane covers 8 halves; 1 metadata load + 1 uint4 gather per edge (vs 2+2 narrow).
template <int MODE>
__global__ void __launch_bounds__(256) k_agg16w(
    const __half* __restrict__ src, __half* __restrict__ dst,
    const float* __restrict__ b, const float* __restrict__ gm,
    const float* __restrict__ be, const float* __restrict__ mn,
    const float* __restrict__ vr) {
    int wid = (blockIdx.x * 256 + threadIdx.x) >> 5;
    int lane = threadIdx.x & 31;
    if (wid >= Nn) return;
    int node = wid;
    const uint4* s4 = (const uint4*)src;   // 32 uint4 per 256-half row
    const uint2* cp = g_csr;
    const __half2 hz = __floats2half2_rn(0.f, 0.f);
    int base = node * 32 + lane;

    float s0 = g_dinv[node];
    s0 *= s0;
    uint4 sv = s4[base];
    float2 q0 = __half22float2(*(__half2*)&sv.x);
    float2 q1 = __half22float2(*(__half2*)&sv.y);
    float2 q2 = __half22float2(*(__half2*)&sv.z);
    float2 q3 = __half22float2(*(__half2*)&sv.w);
    float acc[8] = {s0 * q0.x, s0 * q0.y, s0 * q1.x, s0 * q1.y,
                    s0 * q2.x, s0 * q2.y, s0 * q3.x, s0 * q3.y};

    int e = g_off[node];
    int e1 = g_off[node + 1];
#define WACC(j)                                                       \
    {                                                                 \
        __half2 w_ = *(__half2*)&m[j].y;                              \
        a0 = __hfma2(w_, *(__half2*)&v[j].x, a0);                     \
        a1 = __hfma2(w_, *(__half2*)&v[j].y, a1);                     \
        a2 = __hfma2(w_, *(__half2*)&v[j].z, a2);                     \
        a3 = __hfma2(w_, *(__half2*)&v[j].w, a3);                     \
    }
#define WFLUSH()                                                      \
    {                                                                 \
        float2 f0_ = __half22float2(a0);                              \
        float2 f1_ = __half22float2(a1);                              \
        float2 f2_ = __half22float2(a2);                              \
        float2 f3_ = __half22float2(a3);                              \
        acc[0] += f0_.x; acc[1] += f0_.y; acc[2] += f1_.x; acc[3] += f1_.y; \
        acc[4] += f2_.x; acc[5] += f2_.y; acc[6] += f3_.x; acc[7] += f3_.y; \
    }
    for (; e + 4 <= e1; e += 4) {
        uint2 m[4];
        uint4 v[4];
#pragma unroll
        for (int j = 0; j < 4; j++) m[j] = cp[e + j];
#pragma unroll
        for (int j = 0; j < 4; j++) v[j] = s4[m[j].x * 32 + lane];
        __half2 a0 = hz, a1 = hz, a2 = hz, a3 = hz;
#pragma unroll
        for (int j = 0; j < 4; j++) WACC(j);
        WFLUSH();
    }
    if (e < e1) {
        uint2 m[4];
        uint4 v[4];
#pragma unroll
        for (int j = 0; j < 4; j++) {
            int idx = e + j;
            uint2 mm = make_uint2(0u, 0u);
            if (idx < e1) mm = cp[idx];
            m[j] = mm;
        }
#pragma unroll
        for (int j = 0; j < 4; j++) v[j] = s4[m[j].x * 32 + lane];
        __half2 a0 = hz, a1 = hz, a2 = hz, a3 = hz;
#pragma unroll
        for (int j = 0; j < 4; j++) WACC(j);
        WFLUSH();
    }

    if (MODE == 1) {
        float bv[8], gv[8], bev[8], mv[8], vv[8];
        *(float4*)&bv[0] = ((const float4*)b)[lane * 2];
        *(float4*)&bv[4] = ((const float4*)b)[lane * 2 + 1];
        *(float4*)&gv[0] = ((const float4*)gm)[lane * 2];
        *(float4*)&gv[4] = ((const float4*)gm)[lane * 2 + 1];
        *(float4*)&bev[0] = ((const float4*)be)[lane * 2];
        *(float4*)&bev[4] = ((const float4*)be)[lane * 2 + 1];
        *(float4*)&mv[0] = ((const float4*)mn)[lane * 2];
        *(float4*)&mv[4] = ((const float4*)mn)[lane * 2 + 1];
        *(float4*)&vv[0] = ((const float4*)vr)[lane * 2];
        *(float4*)&vv[4] = ((const float4*)vr)[lane * 2 + 1];
#pragma unroll
        for (int k = 0; k < 8; k++) {
            float s = gv[k] * rsqrtf(vv[k] + 1e-3f);
            float val = (acc[k] + bv[k] - mv[k]) * s + bev[k];
            acc[k] = 1.f / (1.f + __expf(-val));
        }
    }
    __half2 h0 = __floats2half2_rn(acc[0], acc[1]);
    __half2 h1 = __floats2half2_rn(acc[2], acc[3]);
    __half2 h2 = __floats2half2_rn(acc[4], acc[5]);
    __half2 h3 = __floats2half2_rn(acc[6], acc[7]);
    uint4 o;
    o.x = *(uint32_t*)&h0;
    o.y = *(uint32_t*)&h1;
    o.z = *(uint32_t*)&h2;
    o.w = *(uint32_t*)&h3;
    ((uint4*)dst)[base] = o;
}

// ---------------- fp16 mma.sync GEMM (m16n8k16), double-buffered cp.async ----------------
__device__ __forceinline__ void mma_f16(float* c, const uint32_t* a, const uint32_t* b) {
    asm volatile(
        "mma.sync.aligned.m16n8k16.row.col.f32.f16.f16.f32 "
        "{%0,%1,%2,%3}, {%4,%5,%6,%7}, {%8,%9}, {%0,%1,%2,%3};"
        : "+f"(c[0]), "+f"(c[1]), "+f"(c[2]), "+f"(c[3])
        : "r"(a[0]), "r"(a[1]), "r"(a[2]), "r"(a[3]), "r"(b[0]), "r"(b[1]));
}
__device__ __forceinline__ void cpa16(uint32_t smaddr, const void* g, int srcbytes) {
    asm volatile("cp.async.ca.shared.global [%0], [%1], 16, %2;"
                 :: "r"(smaddr), "l"(g), "r"(srcbytes) : "memory");
}
#define CP_COMMIT() asm volatile("cp.async.commit_group;" ::: "memory")
__device__ __forceinline__ uint32_t smem_u32(const void* p) {
    uint32_t a;
    asm("{ .reg .u64 t; cvta.to.shared.u64 t, %1; cvt.u32.u64 %0, t; }" : "=r"(a) : "l"(p));
    return a;
}

// tile: 128 rows x 32 halves, row stride 40 halves (20 words) -> conflict-free frags
#define TW 2560  // words per tile buffer

// EP: 0 raw, 1 sigmoid(BN(c+bias)), 2 sigmoid(c+bias); OUTH: 1 fp16 out, 0 fp32 out
template <int EP, int OUTH>
__global__ void __launch_bounds__(256, 2) k_tgemm(
    const __half* __restrict__ A, const __half* __restrict__ Bt, void* __restrict__ Cv,
    int M, int K, int Nc,
    const float* __restrict__ bias, const float* __restrict__ gm,
    const float* __restrict__ bt, const float* __restrict__ mn,
    const float* __restrict__ vr) {
    __shared__ uint32_t sm[4 * TW];  // A0, A1, B0, B1
    uint32_t sb = smem_u32(sm);
    int t = threadIdx.x;
    int wid = t >> 5, lane = t & 31;
    int warp_m = wid & 1, warp_n = wid >> 1;  // 2 x 4 warps -> 128 x 128
    int m0 = blockIdx.x * 128, n0 = blockIdx.y * 128;
    int g4 = lane >> 2, l4 = lane & 3;

    float acc[4][4][4];
#pragma unroll
    for (int a = 0; a < 4; a++)
#pragma unroll
        for (int b = 0; b < 4; b++)
#pragma unroll
            for (int c = 0; c < 4; c++) acc[a][b][c] = 0.f;

    int fr[2], fq[2];
#pragma unroll
    for (int i = 0; i < 2; i++) {
        int f = t + 256 * i;
        fr[i] = f >> 2;        // row
        fq[i] = f & 3;         // 16B chunk within row (8 halves)
    }

    int nch = K >> 5;
    {
        uint32_t a_s = sb, b_s = sb + 2 * TW * 4;
#pragma unroll
        for (int i = 0; i < 2; i++) {
            int grow = m0 + fr[i];
            const __half* srcA = A + (long)(grow < M ? grow : 0) * K + fq[i] * 8;
            cpa16(a_s + (fr[i] * 20 + fq[i] * 4) * 4, srcA, grow < M ? 16 : 0);
            const __half* srcB = Bt + (long)(n0 + fr[i]) * K + fq[i] * 8;
            cpa16(b_s + (fr[i] * 20 + fq[i] * 4) * 4, srcB, 16);
        }
        CP_COMMIT();
    }

    for (int kc = 0; kc < nch; kc++) {
        if (kc + 1 < nch) {
            int buf = (kc + 1) & 1;
            int k0 = (kc + 1) << 5;
            uint32_t a_s = sb + buf * TW * 4;
            uint32_t b_s = sb + (2 * TW + buf * TW) * 4;
#pragma unroll
            for (int i = 0; i < 2; i++) {
                int grow = m0 + fr[i];
                const __half* srcA = A + (long)(grow < M ? grow : 0) * K + k0 + fq[i] * 8;
                cpa16(a_s + (fr[i] * 20 + fq[i] * 4) * 4, srcA, grow < M ? 16 : 0);
                const __half* srcB = Bt + (long)(n0 + fr[i]) * K + k0 + fq[i] * 8;
                cpa16(b_s + (fr[i] * 20 + fq[i] * 4) * 4, srcB, 16);
            }
            CP_COMMIT();
            asm volatile("cp.async.wait_group 1;" ::: "memory");
        } else {
            asm volatile("cp.async.wait_group 0;" ::: "memory");
        }
        __syncthreads();

        const uint32_t* Ab = sm + (kc & 1) * TW;
        const uint32_t* Bb = sm + 2 * TW + (kc & 1) * TW;
#pragma unroll
        for (int ks = 0; ks < 2; ks++) {
            int kk = ks * 8;  // word offset (16 halves)
            uint32_t af[4][4], bf[4][2];
#pragma unroll
            for (int mt = 0; mt < 4; mt++) {
                int mr = warp_m * 64 + mt * 16 + g4;
                const uint32_t* p = &Ab[mr * 20 + kk + l4];
                af[mt][0] = p[0];
                af[mt][1] = p[8 * 20];
                af[mt][2] = p[4];
                af[mt][3] = p[8 * 20 + 4];
            }
#pragma unroll
            for (int nt = 0; nt < 4; nt++) {
                int nr = warp_n * 32 + nt * 8 + g4;
                const uint32_t* p = &Bb[nr * 20 + kk + l4];
                bf[nt][0] = p[0];
                bf[nt][1] = p[4];
            }
#pragma unroll
            for (int mt = 0; mt < 4; mt++)
#pragma unroll
                for (int nt = 0; nt < 4; nt++) mma_f16(acc[mt][nt], af[mt], bf[nt]);
        }
        __syncthreads();
    }

    // epilogue
#pragma unroll
    for (int mt = 0; mt < 4; mt++) {
        int r = m0 + warp_m * 64 + mt * 16 + g4;
#pragma unroll
        for (int nt = 0; nt < 4; nt++) {
            int j0 = n0 + warp_n * 32 + nt * 8 + l4 * 2;
            float s0 = 1.f, o0 = 0.f, s1 = 1.f, o1 = 0.f;
            if (EP == 1) {
                s0 = gm[j0] * rsqrtf(vr[j0] + 1e-3f);
                o0 = (bias[j0] - mn[j0]) * s0 + bt[j0];
                s1 = gm[j0 + 1] * rsqrtf(vr[j0 + 1] + 1e-3f);
                o1 = (bias[j0 + 1] - mn[j0 + 1]) * s1 + bt[j0 + 1];
            } else if (EP == 2) {
                o0 = bias[j0];
                o1 = bias[j0 + 1];
            }
#pragma unroll
            for (int h = 0; h < 2; h++) {
                int rr = r + h * 8;
                if (rr >= M) continue;
                float v0 = acc[mt][nt][h * 2 + 0];
                float v1 = acc[mt][nt][h * 2 + 1];
                if (EP != 0) {
                    v0 = v0 * s0 + o0;
                    v1 = v1 * s1 + o1;
                    v0 = 1.f / (1.f + __expf(-v0));
                    v1 = 1.f / (1.f + __expf(-v1));
                }
                if (OUTH) {
                    __half2 hv = __floats2half2_rn(v0, v1);
                    *(__half2*)((__half*)Cv + (long)rr * Nc + j0) = hv;
                } else {
                    *(float2*)((float*)Cv + (long)rr * Nc + j0) = make_float2(v0, v1);
                }
            }
        }
    }
}

// ---------------- Z = h^T h (fp32 for accuracy) ----------------
__global__ void __launch_bounds__(256) k_hth(const float* __restrict__ h, int M) {
    __shared__ float sh[32][128];
    int t = threadIdx.x;
    int tx = t & 15, ty = t >> 4;
    int i0 = ty * 8, j0 = tx * 8;
    float acc[8][8];
#pragma unroll
    for (int a = 0; a < 8; a++)
#pragma unroll
        for (int b = 0; b < 8; b++) acc[a][b] = 0.f;

    int rpb = (M + gridDim.x - 1) / gridDim.x;
    int r0 = blockIdx.x * rpb;
    int r1 = min(M, r0 + rpb);
    for (int rb = r0; rb < r1; rb += 32) {
        int nrows = min(32, r1 - rb);
        for (int i = t; i < nrows * 32; i += 256) {
            int rr = i >> 5, c4 = i & 31;
            ((float4*)&sh[rr][0])[c4] = ((const float4*)(h + (long)(rb + rr) * 128))[c4];
        }
        __syncthreads();
        for (int r = 0; r < nrows; r++) {
            float4 a0 = *(const float4*)&sh[r][i0];
            float4 a1 = *(const float4*)&sh[r][i0 + 4];
            float4 b0 = *(const float4*)&sh[r][j0];
            float4 b1 = *(const float4*)&sh[r][j0 + 4];
            float ra[8] = {a0.x, a0.y, a0.z, a0.w, a1.x, a1.y, a1.z, a1.w};
            float rbv[8] = {b0.x, b0.y, b0.z, b0.w, b1.x, b1.y, b1.z, b1.w};
#pragma unroll
            for (int a = 0; a < 8; a++)
#pragma unroll
                for (int b = 0; b < 8; b++) acc[a][b] += ra[a] * rbv[b];
        }
        __syncthreads();
    }
#pragma unroll
    for (int a = 0; a < 8; a++)
#pragma unroll
        for (int b = 0; b < 8; b++)
            atomicAdd(&g_Z[(i0 + a) * 128 + j0 + b], acc[a][b]);
}

// final output + cleanup for next graph replay (deg/cnt re-zeroed here;
// k_setup's atomics next call rely on it; first call uses static zero-init)
__global__ void k_final(float* __restrict__ out) {
    int i = blockIdx.x * blockDim.x + threadIdx.x;
    if (i < 128 * 128) {
        int r = i >> 7, c = i & 127;
        out[i] = (r == c) ? 0.f : 0.5f * (g_Z[r * 128 + c] + g_Z[c * 128 + r]);
    }
    if (i < Nn) {
        g_deg[i] = 0.f;
        g_cnt[i] = 0;
    }
}

// ---------------- launch ----------------
extern "C" void kernel_launch(void* const* d_in, const int* in_sizes, int n_in,
                              void* d_out, int out_size) {
    const float* x = (const float*)d_in[0];
    const int* ei = (const int*)d_in[1];
    const float* ea = (const float*)d_in[2];
    const float *W[5], *bb[5];
    for (int i = 0; i < 5; i++) {
        W[i] = (const float*)d_in[3 + 2 * i];
        bb[i] = (const float*)d_in[4 + 2 * i];
    }
    const float *g[4], *be[4], *mn[4], *vr[4];
    for (int i = 0; i < 4; i++) {
        g[i] = (const float*)d_in[13 + 4 * i];
        be[i] = (const float*)d_in[14 + 4 * i];
        mn[i] = (const float*)d_in[15 + 4 * i];
        vr[i] = (const float*)d_in[16 + 4 * i];
    }
    const int* row = ei;
    const int* col = ei + Ee;

    float *A, *Bf, *WT;
    cudaGetSymbolAddress((void**)&A, g_bufA);
    cudaGetSymbolAddress((void**)&Bf, g_bufB);
    cudaGetSymbolAddress((void**)&WT, g_wT);
    __half* Ah = (__half*)A;
    __half* Bh = (__half*)Bf;
    __half* WTh = (__half*)WT;
    __half* Wt1 = WTh + 0;       // 256x128
    __half* Wt2 = WTh + 32768;   // 512x256
    __half* Wt3 = WTh + 163840;  // 256x512
    __half* Wt4 = WTh + 294912;  // 128x256
    __half* Wt5 = WTh + 327680;  // 128x128

    const int TB = 256;
    // ---- fused setup (cast + transpose + deg/cnt atomics + Z zero) + CSR build ----
    k_setup<<<(1500448 + TB - 1) / TB, TB>>>(x, W[0], W[1], W[2], W[3], W[4], col, ea, WTh, Bh);
    k_scan<<<1, 1024>>>();
    k_fill<<<(Ee + TB - 1) / TB, TB>>>(row, col, ea);

    int gb = (Nn * 32 + TB - 1) / TB;  // 2500 blocks: warp per node
    dim3 t157_1(157, 1), t157_2(157, 2), t157_4(157, 4);

    // L1: agg16 narrow (x16: Bh -> Ah, 128)  [launch #4 -> ncu capture slot]
    k_agg16<0><<<gb, TB>>>(Bh, Ah, Nn, nullptr, nullptr, nullptr, nullptr, nullptr);
    k_tgemm<1, 1><<<t157_2, TB>>>(Ah, Wt1, Bh, Nn, 128, 256, bb[0], g[0], be[0], mn[0], vr[0]);

    // L2: agg16 wide (Bh -> Ah, 256); GEMM(256->512)+BN+sig -> Bh
    k_agg16w<0><<<gb, TB>>>(Bh, Ah, nullptr, nullptr, nullptr, nullptr, nullptr);
    k_tgemm<1, 1><<<t157_4, TB>>>(Ah, Wt2, Bh, Nn, 256, 512, bb[1], g[1], be[1], mn[1], vr[1]);

    // L3: GEMM(512->256) raw -> Ah; agg16 wide+bias+BN+sig (Ah -> Bh, 256)
    k_tgemm<0, 1><<<t157_2, TB>>>(Bh, Wt3, Ah, Nn, 512, 256, nullptr, nullptr, nullptr, nullptr, nullptr);
    k_agg16w<1><<<gb, TB>>>(Ah, Bh, bb[2], g[2], be[2], mn[2], vr[2]);

    // L4: GEMM(256->128) raw -> Ah; agg16 narrow+bias+BN+sig (Ah -> Bh, 128)
    k_tgemm<0, 1><<<t157_1, TB>>>(Bh, Wt4, Ah, Nn, 256, 128, nullptr, nullptr, nullptr, nullptr, nullptr);
    k_agg16<1><<<gb, TB>>>(Ah, Bh, Nn, bb[3], g[3], be[3], mn[3], vr[3]);

    // L5: agg16 narrow (Bh -> Ah, 128); GEMM(128->128)+bias+sig -> Bf fp32
    k_agg16<0><<<gb, TB>>>(Bh, Ah, Nn, nullptr, nullptr, nullptr, nullptr, nullptr);
    k_tgemm<2, 0><<<t157_1, TB>>>(Ah, Wt5, Bf, Nn, 128, 128, bb[4], nullptr, nullptr, nullptr, nullptr);

    // final: Z = h^T h (fp32); symmetrize + zero diagonal; cleanup deg/cnt
    k_hth<<<157, TB>>>(Bf, Nn);
    k_final<<<(Nn + TB - 1) / TB, TB>>>((float*)d_out);
}

// round 15
// speedup vs baseline: 1.4423x; 1.4423x over previous
#include <cuda_runtime.h>
#include <cuda_fp16.h>
#include <cstdint>
#include <math.h>

#define Nn 20000
#define Ee 500000

// ---------------- scratch (device globals; no allocation) ----------------
// g_deg / g_cnt are zeroed at the END of each call (cleanup in k_final);
// first call relies on static zero-init of __device__ globals.
__device__ float g_deg[Nn];
__device__ int   g_cnt[Nn];
__device__ float g_dinv[Nn];
__device__ int   g_off[Nn + 1];
__device__ int   g_pos[Nn];
__device__ uint2 g_csr[Ee];      // interleaved (row, half2(w,w) bits)
__device__ float g_bufA[Nn * 512];
__device__ float g_bufB[Nn * 512];
__device__ float g_wT[344064];   // holds 344064 halves (transposed fp16 weights)
__device__ float g_Z[128 * 128];

// ---------------- fused setup: x cast, W transpose, deg/cnt atomics, Z zero ----------------
__global__ void k_setup(const float* __restrict__ x,
                        const float* __restrict__ W1, const float* __restrict__ W2,
                        const float* __restrict__ W3, const float* __restrict__ W4,
                        const float* __restrict__ W5,
                        const int* __restrict__ col, const float* __restrict__ ew,
                        __half* __restrict__ WTh, __half* __restrict__ xh) {
    int i = blockIdx.x * blockDim.x + threadIdx.x;
    if (i < 640000) {  // Nn*32 float4 units: cast x -> fp16
        float4 v = ((const float4*)x)[i];
        __half2 h0 = __floats2half2_rn(v.x, v.y);
        __half2 h1 = __floats2half2_rn(v.z, v.w);
        uint2 o;
        o.x = *(uint32_t*)&h0;
        o.y = *(uint32_t*)&h1;
        ((uint2*)xh)[i] = o;
    } else if (i < 984064) {  // transpose W[K,N] -> Wt[N,K] fp16
        int j = i - 640000;
        if (j < 32768) {
            int k = j >> 8, n = j & 255;
            WTh[n * 128 + k] = __float2half_rn(W1[j]);
        } else if (j < 163840) {
            int q = j - 32768;
            int k = q >> 9, n = q & 511;
            WTh[32768 + n * 256 + k] = __float2half_rn(W2[q]);
        } else if (j < 294912) {
            int q = j - 163840;
            int k = q >> 8, n = q & 255;
            WTh[163840 + n * 512 + k] = __float2half_rn(W3[q]);
        } else if (j < 327680) {
            int q = j - 294912;
            int k = q >> 7, n = q & 127;
            WTh[294912 + n * 256 + k] = __float2half_rn(W4[q]);
        } else {
            int q = j - 327680;
            int k = q >> 7, n = q & 127;
            WTh[327680 + n * 128 + k] = __float2half_rn(W5[q]);
        }
    } else if (i < 1484064) {  // degree + count atomics (deg/cnt pre-zeroed by cleanup)
        int j = i - 984064;
        int c = col[j];
        atomicAdd(&g_deg[c], ew[j]);
        atomicAdd(&g_cnt[c], 1);
    } else if (i < 1500448) {  // zero Z (written only by k_hth, much later)
        g_Z[i - 1484064] = 0.f;
    }
}

// scan of g_cnt -> g_off/g_pos, plus dinv (merged; 1 block, 1024 threads)
__global__ void __launch_bounds__(1024) k_scan() {
    __shared__ int wsum[32];
    int t = threadIdx.x;
    const int C = 20;
    int base = t * C;
    int cnt[C];
    int s = 0;
#pragma unroll
    for (int i = 0; i < C; i++) {
        int idx = base + i;
        int c = 0;
        if (idx < Nn) {
            c = g_cnt[idx];
            g_dinv[idx] = rsqrtf(g_deg[idx] + 1.0f);
        }
        cnt[i] = c;
        s += c;
    }
    int lane = t & 31, w = t >> 5;
    int v = s;
#pragma unroll
    for (int o = 1; o < 32; o <<= 1) {
        int u = __shfl_up_sync(0xFFFFFFFF, v, o);
        if (lane >= o) v += u;
    }
    if (lane == 31) wsum[w] = v;
    __syncthreads();
    if (w == 0) {
        int x = wsum[lane];
#pragma unroll
        for (int o = 1; o < 32; o <<= 1) {
            int u = __shfl_up_sync(0xFFFFFFFF, x, o);
            if (lane >= o) x += u;
        }
        wsum[lane] = x;
    }
    __syncthreads();
    int run = v - s + (w > 0 ? wsum[w - 1] : 0);
#pragma unroll
    for (int i = 0; i < C; i++) {
        int idx = base + i;
        if (idx < Nn) {
            g_off[idx] = run;
            g_pos[idx] = run;
            run += cnt[i];
        }
    }
    if (t == 1023) g_off[Nn] = run;
}

__global__ void k_fill(const int* __restrict__ row, const int* __restrict__ col,
                       const float* __restrict__ w) {
    int i = blockIdx.x * blockDim.x + threadIdx.x;
    if (i >= Ee) return;
    int r = row[i], c = col[i];
    float nw = g_dinv[r] * w[i] * g_dinv[c];
    int p = atomicAdd(&g_pos[c], 1);
    __half2 wh = __floats2half2_rn(nw, nw);
    uint2 pr;
    pr.x = (uint32_t)r;
    pr.y = *(uint32_t*)&wh;
    g_csr[p] = pr;
}

// ---------------- atomic-free aggregation, fp16 HFMA2 inner loop (R12 proven) ----------------
#define HACC_EDGE(mm, vv)                                             \
    {                                                                 \
        __half2 w_ = *(__half2*)&(mm).y;                              \
        a0 = __hfma2(w_, *(__half2*)&(vv).x, a0);                     \
        a1 = __hfma2(w_, *(__half2*)&(vv).y, a1);                     \
    }
#define HFLUSH()                                                      \
    {                                                                 \
        float2 f0_ = __half22float2(a0);                              \
        float2 f1_ = __half22float2(a1);                              \
        acc.x += f0_.x; acc.y += f0_.y;                               \
        acc.z += f1_.x; acc.w += f1_.y;                               \
    }

// MODE 0: raw agg; MODE 1: agg + bias + BN + sigmoid
template <int MODE>
__global__ void __launch_bounds__(256) k_agg16(
    const __half* __restrict__ src, __half* __restrict__ dst,
    int nchl, int total_w,
    const float* __restrict__ b, const float* __restrict__ gm,
    const float* __restrict__ be, const float* __restrict__ mn,
    const float* __restrict__ vr) {
    int wid = (blockIdx.x * 256 + threadIdx.x) >> 5;
    int lane = threadIdx.x & 31;
    if (wid >= total_w) return;
    int node = wid >> nchl;
    int chunk = wid & ((1 << nchl) - 1);
    int du = 32 << nchl;            // uint2 (4-half) units per row
    int cw = chunk * 32 + lane;
    const uint2* s2 = (const uint2*)src;
    const uint2* cp = g_csr;
    const __half2 hz = __floats2half2_rn(0.f, 0.f);

    float s0 = g_dinv[node];
    s0 *= s0;
    uint2 sv = s2[node * du + cw];
    float2 p0 = __half22float2(*(__half2*)&sv.x);
    float2 p1 = __half22float2(*(__half2*)&sv.y);
    float4 acc = make_float4(s0 * p0.x, s0 * p0.y, s0 * p1.x, s0 * p1.y);

    int e = g_off[node];
    int e1 = g_off[node + 1];
    // 8-edge batches: independent loads for MLP, HFMA2 accumulate, fp32 flush
    for (; e + 8 <= e1; e += 8) {
        uint2 m[8], v[8];
#pragma unroll
        for (int j = 0; j < 8; j++) m[j] = cp[e + j];
#pragma unroll
        for (int j = 0; j < 8; j++) v[j] = s2[m[j].x * du + cw];
        __half2 a0 = hz, a1 = hz;
#pragma unroll
        for (int j = 0; j < 8; j++) HACC_EDGE(m[j], v[j]);
        HFLUSH();
    }
    // masked final batch (remainder <8 padded with w=0)
    if (e < e1) {
        uint2 m[8], v[8];
#pragma unroll
        for (int j = 0; j < 8; j++) {
            int idx = e + j;
            uint2 mm = make_uint2(0u, 0u);
            if (idx < e1) mm = cp[idx];
            m[j] = mm;
        }
#pragma unroll
        for (int j = 0; j < 8; j++) v[j] = s2[m[j].x * du + cw];
        __half2 a0 = hz, a1 = hz;
#pragma unroll
        for (int j = 0; j < 8; j++) HACC_EDGE(m[j], v[j]);
        HFLUSH();
    }

    if (MODE == 1) {
        float4 bv = ((const float4*)b)[cw];
        float4 gv = ((const float4*)gm)[cw];
        float4 bev = ((const float4*)be)[cw];
        float4 mv = ((const float4*)mn)[cw];
        float4 vv = ((const float4*)vr)[cw];
        float sx = gv.x * rsqrtf(vv.x + 1e-3f);
        float sy = gv.y * rsqrtf(vv.y + 1e-3f);
        float sz = gv.z * rsqrtf(vv.z + 1e-3f);
        float sw = gv.w * rsqrtf(vv.w + 1e-3f);
        acc.x = (acc.x + bv.x - mv.x) * sx + bev.x;
        acc.y = (acc.y + bv.y - mv.y) * sy + bev.y;
        acc.z = (acc.z + bv.z - mv.z) * sz + bev.z;
        acc.w = (acc.w + bv.w - mv.w) * sw + bev.w;
        acc.x = 1.f / (1.f + __expf(-acc.x));
        acc.y = 1.f / (1.f + __expf(-acc.y));
        acc.z = 1.f / (1.f + __expf(-acc.z));
        acc.w = 1.f / (1.f + __expf(-acc.w));
    }
    __half2 h0 = __floats2half2_rn(acc.x, acc.y);
    __half2 h1 = __floats2half2_rn(acc.z, acc.w);
    uint2 o;
    o.x = *(uint32_t*)&h0;
    o.y = *(uint32_t*)&h1;
    ((uint2*)dst)[node * du + cw] = o;
}

// ---------------- fp16 mma.sync GEMM (m16n8k16), double-buffered cp.async ----------------
__device__ __forceinline__ void mma_f16(float* c, const uint32_t* a, const uint32_t* b) {
    asm volatile(
        "mma.sync.aligned.m16n8k16.row.col.f32.f16.f16.f32 "
        "{%0,%1,%2,%3}, {%4,%5,%6,%7}, {%8,%9}, {%0,%1,%2,%3};"
        : "+f"(c[0]), "+f"(c[1]), "+f"(c[2]), "+f"(c[3])
        : "r"(a[0]), "r"(a[1]), "r"(a[2]), "r"(a[3]), "r"(b[0]), "r"(b[1]));
}
__device__ __forceinline__ void cpa16(uint32_t smaddr, const void* g, int srcbytes) {
    asm volatile("cp.async.ca.shared.global [%0], [%1], 16, %2;"
                 :: "r"(smaddr), "l"(g), "r"(srcbytes) : "memory");
}
#define CP_COMMIT() asm volatile("cp.async.commit_group;" ::: "memory")
__device__ __forceinline__ uint32_t smem_u32(const void* p) {
    uint32_t a;
    asm("{ .reg .u64 t; cvta.to.shared.u64 t, %1; cvt.u32.u64 %0, t; }" : "=r"(a) : "l"(p));
    return a;
}

// tile: 128 rows x 32 halves, row stride 40 halves (20 words) -> conflict-free frags
#define TW 2560  // words per tile buffer

// EP: 0 raw, 1 sigmoid(BN(c+bias)), 2 sigmoid(c+bias); OUTH: 1 fp16 out, 0 fp32 out
template <int EP, int OUTH>
__global__ void __launch_bounds__(256, 2) k_tgemm(
    const __half* __restrict__ A, const __half* __restrict__ Bt, void* __restrict__ Cv,
    int M, int K, int Nc,
    const float* __restrict__ bias, const float* __restrict__ gm,
    const float* __restrict__ bt, const float* __restrict__ mn,
    const float* __restrict__ vr) {
    __shared__ uint32_t sm[4 * TW];  // A0, A1, B0, B1
    uint32_t sb = smem_u32(sm);
    int t = threadIdx.x;
    int wid = t >> 5, lane = t & 31;
    int warp_m = wid & 1, warp_n = wid >> 1;  // 2 x 4 warps -> 128 x 128
    int m0 = blockIdx.x * 128, n0 = blockIdx.y * 128;
    int g4 = lane >> 2, l4 = lane & 3;

    float acc[4][4][4];
#pragma unroll
    for (int a = 0; a < 4; a++)
#pragma unroll
        for (int b = 0; b < 4; b++)
#pragma unroll
            for (int c = 0; c < 4; c++) acc[a][b][c] = 0.f;

    int fr[2], fq[2];
#pragma unroll
    for (int i = 0; i < 2; i++) {
        int f = t + 256 * i;
        fr[i] = f >> 2;        // row
        fq[i] = f & 3;         // 16B chunk within row (8 halves)
    }

    int nch = K >> 5;
    {
        uint32_t a_s = sb, b_s = sb + 2 * TW * 4;
#pragma unroll
        for (int i = 0; i < 2; i++) {
            int grow = m0 + fr[i];
            const __half* srcA = A + (long)(grow < M ? grow : 0) * K + fq[i] * 8;
            cpa16(a_s + (fr[i] * 20 + fq[i] * 4) * 4, srcA, grow < M ? 16 : 0);
            const __half* srcB = Bt + (long)(n0 + fr[i]) * K + fq[i] * 8;
            cpa16(b_s + (fr[i] * 20 + fq[i] * 4) * 4, srcB, 16);
        }
        CP_COMMIT();
    }

    for (int kc = 0; kc < nch; kc++) {
        if (kc + 1 < nch) {
            int buf = (kc + 1) & 1;
            int k0 = (kc + 1) << 5;
            uint32_t a_s = sb + buf * TW * 4;
            uint32_t b_s = sb + (2 * TW + buf * TW) * 4;
#pragma unroll
            for (int i = 0; i < 2; i++) {
                int grow = m0 + fr[i];
                const __half* srcA = A + (long)(grow < M ? grow : 0) * K + k0 + fq[i] * 8;
                cpa16(a_s + (fr[i] * 20 + fq[i] * 4) * 4, srcA, grow < M ? 16 : 0);
                const __half* srcB = Bt + (long)(n0 + fr[i]) * K + k0 + fq[i] * 8;
                cpa16(b_s + (fr[i] * 20 + fq[i] * 4) * 4, srcB, 16);
            }
            CP_COMMIT();
            asm volatile("cp.async.wait_group 1;" ::: "memory");
        } else {
            asm volatile("cp.async.wait_group 0;" ::: "memory");
        }
        __syncthreads();

        const uint32_t* Ab = sm + (kc & 1) * TW;
        const uint32_t* Bb = sm + 2 * TW + (kc & 1) * TW;
#pragma unroll
        for (int ks = 0; ks < 2; ks++) {
            int kk = ks * 8;  // word offset (16 halves)
            uint32_t af[4][4], bf[4][2];
#pragma unroll
            for (int mt = 0; mt < 4; mt++) {
                int mr = warp_m * 64 + mt * 16 + g4;
                const uint32_t* p = &Ab[mr * 20 + kk + l4];
                af[mt][0] = p[0];
                af[mt][1] = p[8 * 20];
                af[mt][2] = p[4];
                af[mt][3] = p[8 * 20 + 4];
            }
#pragma unroll
            for (int nt = 0; nt < 4; nt++) {
                int nr = warp_n * 32 + nt * 8 + g4;
                const uint32_t* p = &Bb[nr * 20 + kk + l4];
                bf[nt][0] = p[0];
                bf[nt][1] = p[4];
            }
#pragma unroll
            for (int mt = 0; mt < 4; mt++)
#pragma unroll
                for (int nt = 0; nt < 4; nt++) mma_f16(acc[mt][nt], af[mt], bf[nt]);
        }
        __syncthreads();
    }

    // epilogue
#pragma unroll
    for (int mt = 0; mt < 4; mt++) {
        int r = m0 + warp_m * 64 + mt * 16 + g4;
#pragma unroll
        for (int nt = 0; nt < 4; nt++) {
            int j0 = n0 + warp_n * 32 + nt * 8 + l4 * 2;
            float s0 = 1.f, o0 = 0.f, s1 = 1.f, o1 = 0.f;
            if (EP == 1) {
                s0 = gm[j0] * rsqrtf(vr[j0] + 1e-3f);
                o0 = (bias[j0] - mn[j0]) * s0 + bt[j0];
                s1 = gm[j0 + 1] * rsqrtf(vr[j0 + 1] + 1e-3f);
                o1 = (bias[j0 + 1] - mn[j0 + 1]) * s1 + bt[j0 + 1];
            } else if (EP == 2) {
                o0 = bias[j0];
                o1 = bias[j0 + 1];
            }
#pragma unroll
            for (int h = 0; h < 2; h++) {
                int rr = r + h * 8;
                if (rr >= M) continue;
                float v0 = acc[mt][nt][h * 2 + 0];
                float v1 = acc[mt][nt][h * 2 + 1];
                if (EP != 0) {
                    v0 = v0 * s0 + o0;
                    v1 = v1 * s1 + o1;
                    v0 = 1.f / (1.f + __expf(-v0));
                    v1 = 1.f / (1.f + __expf(-v1));
                }
                if (OUTH) {
                    __half2 hv = __floats2half2_rn(v0, v1);
                    *(__half2*)((__half*)Cv + (long)rr * Nc + j0) = hv;
                } else {
                    *(float2*)((float*)Cv + (long)rr * Nc + j0) = make_float2(v0, v1);
                }
            }
        }
    }
}

// ---------------- Z = h^T h (fp16 input, fp32 accumulate) ----------------
__global__ void __launch_bounds__(256) k_hth(const __half* __restrict__ h, int M) {
    __shared__ float sh[32][128];
    int t = threadIdx.x;
    int tx = t & 15, ty = t >> 4;
    int i0 = ty * 8, j0 = tx * 8;
    float acc[8][8];
#pragma unroll
    for (int a = 0; a < 8; a++)
#pragma unroll
        for (int b = 0; b < 8; b++) acc[a][b] = 0.f;

    int rpb = (M + gridDim.x - 1) / gridDim.x;
    int r0 = blockIdx.x * rpb;
    int r1 = min(M, r0 + rpb);
    for (int rb = r0; rb < r1; rb += 32) {
        int nrows = min(32, r1 - rb);
        // stage fp16 rows into fp32 smem (16 uint4 = 128 halves per row)
        for (int i = t; i < nrows * 16; i += 256) {
            int rr = i >> 4, c8 = i & 15;
            uint4 v = ((const uint4*)(h + (long)(rb + rr) * 128))[c8];
            float* d = &sh[rr][c8 * 8];
            float2 f0 = __half22float2(*(__half2*)&v.x);
            float2 f1 = __half22float2(*(__half2*)&v.y);
            float2 f2 = __half22float2(*(__half2*)&v.z);
            float2 f3 = __half22float2(*(__half2*)&v.w);
            d[0] = f0.x; d[1] = f0.y; d[2] = f1.x; d[3] = f1.y;
            d[4] = f2.x; d[5] = f2.y; d[6] = f3.x; d[7] = f3.y;
        }
        __syncthreads();
        for (int r = 0; r < nrows; r++) {
            float4 a0 = *(const float4*)&sh[r][i0];
            float4 a1 = *(const float4*)&sh[r][i0 + 4];
            float4 b0 = *(const float4*)&sh[r][j0];
            float4 b1 = *(const float4*)&sh[r][j0 + 4];
            float ra[8] = {a0.x, a0.y, a0.z, a0.w, a1.x, a1.y, a1.z, a1.w};
            float rbv[8] = {b0.x, b0.y, b0.z, b0.w, b1.x, b1.y, b1.z, b1.w};
#pragma unroll
            for (int a = 0; a < 8; a++)
#pragma unroll
                for (int b = 0; b < 8; b++) acc[a][b] += ra[a] * rbv[b];
        }
        __syncthreads();
    }
#pragma unroll
    for (int a = 0; a < 8; a++)
#pragma unroll
        for (int b = 0; b < 8; b++)
            atomicAdd(&g_Z[(i0 + a) * 128 + j0 + b], acc[a][b]);
}

// final output + cleanup for next graph replay (deg/cnt re-zeroed here;
// k_setup's atomics next call rely on it; first call uses static zero-init)
__global__ void k_final(float* __restrict__ out) {
    int i = blockIdx.x * blockDim.x + threadIdx.x;
    if (i < 128 * 128) {
        int r = i >> 7, c = i & 127;
        out[i] = (r == c) ? 0.f : 0.5f * (g_Z[r * 128 + c] + g_Z[c * 128 + r]);
    }
    if (i < Nn) {
        g_deg[i] = 0.f;
        g_cnt[i] = 0;
    }
}

// ---------------- launch ----------------
extern "C" void kernel_launch(void* const* d_in, const int* in_sizes, int n_in,
                              void* d_out, int out_size) {
    const float* x = (const float*)d_in[0];
    const int* ei = (const int*)d_in[1];
    const float* ea = (const float*)d_in[2];
    const float *W[5], *bb[5];
    for (int i = 0; i < 5; i++) {
        W[i] = (const float*)d_in[3 + 2 * i];
        bb[i] = (const float*)d_in[4 + 2 * i];
    }
    const float *g[4], *be[4], *mn[4], *vr[4];
    for (int i = 0; i < 4; i++) {
        g[i] = (const float*)d_in[13 + 4 * i];
        be[i] = (const float*)d_in[14 + 4 * i];
        mn[i] = (const float*)d_in[15 + 4 * i];
        vr[i] = (const float*)d_in[16 + 4 * i];
    }
    const int* row = ei;
    const int* col = ei + Ee;

    float *A, *Bf, *WT;
    cudaGetSymbolAddress((void**)&A, g_bufA);
    cudaGetSymbolAddress((void**)&Bf, g_bufB);
    cudaGetSymbolAddress((void**)&WT, g_wT);
    __half* Ah = (__half*)A;
    __half* Bh = (__half*)Bf;
    __half* WTh = (__half*)WT;
    __half* Wt1 = WTh + 0;       // 256x128
    __half* Wt2 = WTh + 32768;   // 512x256
    __half* Wt3 = WTh + 163840;  // 256x512
    __half* Wt4 = WTh + 294912;  // 128x256
    __half* Wt5 = WTh + 327680;  // 128x128

    const int TB = 256;
    // ---- fused setup (cast + transpose + deg/cnt atomics + Z zero) + CSR build ----
    k_setup<<<(1500448 + TB - 1) / TB, TB>>>(x, W[0], W[1], W[2], W[3], W[4], col, ea, WTh, Bh);
    k_scan<<<1, 1024>>>();
    k_fill<<<(Ee + TB - 1) / TB, TB>>>(row, col, ea);

    int w1 = Nn, w2 = Nn * 2;
    int gb1 = (w1 * 32 + TB - 1) / TB;
    int gb2 = (w2 * 32 + TB - 1) / TB;
    dim3 t157_1(157, 1), t157_2(157, 2), t157_4(157, 4);

    // L1: agg16(x16: Bh -> Ah, 128)  [launch #4 -> ncu capture slot]
    k_agg16<0><<<gb1, TB>>>(Bh, Ah, 0, w1, nullptr, nullptr, nullptr, nullptr, nullptr);
    k_tgemm<1, 1><<<t157_2, TB>>>(Ah, Wt1, Bh, Nn, 128, 256, bb[0], g[0], be[0], mn[0], vr[0]);

    // L2: agg16(Bh -> Ah, 256); GEMM(256->512)+BN+sig -> Bh
    k_agg16<0><<<gb2, TB>>>(Bh, Ah, 1, w2, nullptr, nullptr, nullptr, nullptr, nullptr);
    k_tgemm<1, 1><<<t157_4, TB>>>(Ah, Wt2, Bh, Nn, 256, 512, bb[1], g[1], be[1], mn[1], vr[1]);

    // L3: GEMM(512->256) raw -> Ah; agg16+bias+BN+sig (Ah -> Bh, 256)
    k_tgemm<0, 1><<<t157_2, TB>>>(Bh, Wt3, Ah, Nn, 512, 256, nullptr, nullptr, nullptr, nullptr, nullptr);
    k_agg16<1><<<gb2, TB>>>(Ah, Bh, 1, w2, bb[2], g[2], be[2], mn[2], vr[2]);

    // L4: GEMM(256->128) raw -> Ah; agg16+bias+BN+sig (Ah -> Bh, 128)
    k_tgemm<0, 1><<<t157_1, TB>>>(Bh, Wt4, Ah, Nn, 256, 128, nullptr, nullptr, nullptr, nullptr, nullptr);
    k_agg16<1><<<gb1, TB>>>(Ah, Bh, 0, w1, bb[3], g[3], be[3], mn[3], vr[3]);

    // L5: agg16(Bh -> Ah, 128); GEMM(128->128)+bias+sig -> h5 fp16 in Bh
    k_agg16<0><<<gb1, TB>>>(Bh, Ah, 0, w1, nullptr, nullptr, nullptr, nullptr, nullptr);
    k_tgemm<2, 1><<<t157_1, TB>>>(Ah, Wt5, Bh, Nn, 128, 128, bb[4], nullptr, nullptr, nullptr, nullptr);

    // final: Z = h^T h (fp16 in, fp32 acc); symmetrize + zero diagonal; cleanup
    k_hth<<<157, TB>>>(Bh, Nn);
    k_final<<<(Nn + TB - 1) / TB, TB>>>((float*)d_out);
}

// round 16
// speedup vs baseline: 1.4824x; 1.0278x over previous
#include <cuda_runtime.h>
#include <cuda_fp16.h>
#include <cstdint>
#include <math.h>

#define Nn 20000
#define Ee 500000

// PDL: dependent-launch wait/trigger (sm_90+)
#define PDL_WAIT() asm volatile("griddepcontrol.wait;" ::: "memory")
#define PDL_TRIGGER() asm volatile("griddepcontrol.launch_dependents;" ::: "memory")

// ---------------- scratch (device globals; no allocation) ----------------
// g_deg / g_cnt are zeroed at the END of each call (cleanup in k_final);
// first call relies on static zero-init of __device__ globals.
__device__ float g_deg[Nn];
__device__ int   g_cnt[Nn];
__device__ float g_dinv[Nn];
__device__ int   g_off[Nn + 1];
__device__ int   g_pos[Nn];
__device__ uint2 g_csr[Ee];      // interleaved (row, half2(w,w) bits)
__device__ float g_bufA[Nn * 512];
__device__ float g_bufB[Nn * 512];
__device__ float g_wT[344064];   // holds 344064 halves (transposed fp16 weights)
__device__ float g_Z[128 * 128];

// ---------------- fused setup: x cast, W transpose, deg/cnt atomics, Z zero ----------------
__global__ void k_setup(const float* __restrict__ x,
                        const float* __restrict__ W1, const float* __restrict__ W2,
                        const float* __restrict__ W3, const float* __restrict__ W4,
                        const float* __restrict__ W5,
                        const int* __restrict__ col, const float* __restrict__ ew,
                        __half* __restrict__ WTh, __half* __restrict__ xh) {
    int i = blockIdx.x * blockDim.x + threadIdx.x;
    if (i < 640000) {  // Nn*32 float4 units: cast x -> fp16
        float4 v = ((const float4*)x)[i];
        __half2 h0 = __floats2half2_rn(v.x, v.y);
        __half2 h1 = __floats2half2_rn(v.z, v.w);
        uint2 o;
        o.x = *(uint32_t*)&h0;
        o.y = *(uint32_t*)&h1;
        ((uint2*)xh)[i] = o;
    } else if (i < 984064) {  // transpose W[K,N] -> Wt[N,K] fp16
        int j = i - 640000;
        if (j < 32768) {
            int k = j >> 8, n = j & 255;
            WTh[n * 128 + k] = __float2half_rn(W1[j]);
        } else if (j < 163840) {
            int q = j - 32768;
            int k = q >> 9, n = q & 511;
            WTh[32768 + n * 256 + k] = __float2half_rn(W2[q]);
        } else if (j < 294912) {
            int q = j - 163840;
            int k = q >> 8, n = q & 255;
            WTh[163840 + n * 512 + k] = __float2half_rn(W3[q]);
        } else if (j < 327680) {
            int q = j - 294912;
            int k = q >> 7, n = q & 127;
            WTh[294912 + n * 256 + k] = __float2half_rn(W4[q]);
        } else {
            int q = j - 327680;
            int k = q >> 7, n = q & 127;
            WTh[327680 + n * 128 + k] = __float2half_rn(W5[q]);
        }
    } else if (i < 1484064) {  // degree + count atomics (deg/cnt pre-zeroed by cleanup)
        int j = i - 984064;
        int c = col[j];
        atomicAdd(&g_deg[c], ew[j]);
        atomicAdd(&g_cnt[c], 1);
    } else if (i < 1500448) {  // zero Z (written only by k_hth, much later)
        g_Z[i - 1484064] = 0.f;
    }
    PDL_TRIGGER();
}

// scan of g_cnt -> g_off/g_pos, plus dinv (merged; 1 block, 1024 threads)
__global__ void __launch_bounds__(1024) k_scan() {
    PDL_WAIT();
    __shared__ int wsum[32];
    int t = threadIdx.x;
    const int C = 20;
    int base = t * C;
    int cnt[C];
    int s = 0;
#pragma unroll
    for (int i = 0; i < C; i++) {
        int idx = base + i;
        int c = 0;
        if (idx < Nn) {
            c = g_cnt[idx];
            g_dinv[idx] = rsqrtf(g_deg[idx] + 1.0f);
        }
        cnt[i] = c;
        s += c;
    }
    int lane = t & 31, w = t >> 5;
    int v = s;
#pragma unroll
    for (int o = 1; o < 32; o <<= 1) {
        int u = __shfl_up_sync(0xFFFFFFFF, v, o);
        if (lane >= o) v += u;
    }
    if (lane == 31) wsum[w] = v;
    __syncthreads();
    if (w == 0) {
        int x = wsum[lane];
#pragma unroll
        for (int o = 1; o < 32; o <<= 1) {
            int u = __shfl_up_sync(0xFFFFFFFF, x, o);
            if (lane >= o) x += u;
        }
        wsum[lane] = x;
    }
    __syncthreads();
    int run = v - s + (w > 0 ? wsum[w - 1] : 0);
#pragma unroll
    for (int i = 0; i < C; i++) {
        int idx = base + i;
        if (idx < Nn) {
            g_off[idx] = run;
            g_pos[idx] = run;
            run += cnt[i];
        }
    }
    if (t == 1023) g_off[Nn] = run;
    PDL_TRIGGER();
}

__global__ void k_fill(const int* __restrict__ row, const int* __restrict__ col,
                       const float* __restrict__ w) {
    PDL_WAIT();
    int i = blockIdx.x * blockDim.x + threadIdx.x;
    if (i < Ee) {
        int r = row[i], c = col[i];
        float nw = g_dinv[r] * w[i] * g_dinv[c];
        int p = atomicAdd(&g_pos[c], 1);
        __half2 wh = __floats2half2_rn(nw, nw);
        uint2 pr;
        pr.x = (uint32_t)r;
        pr.y = *(uint32_t*)&wh;
        g_csr[p] = pr;
    }
    PDL_TRIGGER();
}

// ---------------- atomic-free aggregation, fp16 HFMA2 inner loop (R12 proven) ----------------
#define HACC_EDGE(mm, vv)                                             \
    {                                                                 \
        __half2 w_ = *(__half2*)&(mm).y;                              \
        a0 = __hfma2(w_, *(__half2*)&(vv).x, a0);                     \
        a1 = __hfma2(w_, *(__half2*)&(vv).y, a1);                     \
    }
#define HFLUSH()                                                      \
    {                                                                 \
        float2 f0_ = __half22float2(a0);                              \
        float2 f1_ = __half22float2(a1);                              \
        acc.x += f0_.x; acc.y += f0_.y;                               \
        acc.z += f1_.x; acc.w += f1_.y;                               \
    }

// MODE 0: raw agg; MODE 1: agg + bias + BN + sigmoid
template <int MODE>
__global__ void __launch_bounds__(256) k_agg16(
    const __half* __restrict__ src, __half* __restrict__ dst,
    int nchl, int total_w,
    const float* __restrict__ b, const float* __restrict__ gm,
    const float* __restrict__ be, const float* __restrict__ mn,
    const float* __restrict__ vr) {
    PDL_WAIT();
    int wid = (blockIdx.x * 256 + threadIdx.x) >> 5;
    int lane = threadIdx.x & 31;
    if (wid >= total_w) return;
    int node = wid >> nchl;
    int chunk = wid & ((1 << nchl) - 1);
    int du = 32 << nchl;            // uint2 (4-half) units per row
    int cw = chunk * 32 + lane;
    const uint2* s2 = (const uint2*)src;
    const uint2* cp = g_csr;
    const __half2 hz = __floats2half2_rn(0.f, 0.f);

    float s0 = g_dinv[node];
    s0 *= s0;
    uint2 sv = s2[node * du + cw];
    float2 p0 = __half22float2(*(__half2*)&sv.x);
    float2 p1 = __half22float2(*(__half2*)&sv.y);
    float4 acc = make_float4(s0 * p0.x, s0 * p0.y, s0 * p1.x, s0 * p1.y);

    int e = g_off[node];
    int e1 = g_off[node + 1];
    // 8-edge batches: independent loads for MLP, HFMA2 accumulate, fp32 flush
    for (; e + 8 <= e1; e += 8) {
        uint2 m[8], v[8];
#pragma unroll
        for (int j = 0; j < 8; j++) m[j] = cp[e + j];
#pragma unroll
        for (int j = 0; j < 8; j++) v[j] = s2[m[j].x * du + cw];
        __half2 a0 = hz, a1 = hz;
#pragma unroll
        for (int j = 0; j < 8; j++) HACC_EDGE(m[j], v[j]);
        HFLUSH();
    }
    // masked final batch (remainder <8 padded with w=0)
    if (e < e1) {
        uint2 m[8], v[8];
#pragma unroll
        for (int j = 0; j < 8; j++) {
            int idx = e + j;
            uint2 mm = make_uint2(0u, 0u);
            if (idx < e1) mm = cp[idx];
            m[j] = mm;
        }
#pragma unroll
        for (int j = 0; j < 8; j++) v[j] = s2[m[j].x * du + cw];
        __half2 a0 = hz, a1 = hz;
#pragma unroll
        for (int j = 0; j < 8; j++) HACC_EDGE(m[j], v[j]);
        HFLUSH();
    }

    if (MODE == 1) {
        float4 bv = ((const float4*)b)[cw];
        float4 gv = ((const float4*)gm)[cw];
        float4 bev = ((const float4*)be)[cw];
        float4 mv = ((const float4*)mn)[cw];
        float4 vv = ((const float4*)vr)[cw];
        float sx = gv.x * rsqrtf(vv.x + 1e-3f);
        float sy = gv.y * rsqrtf(vv.y + 1e-3f);
        float sz = gv.z * rsqrtf(vv.z + 1e-3f);
        float sw = gv.w * rsqrtf(vv.w + 1e-3f);
        acc.x = (acc.x + bv.x - mv.x) * sx + bev.x;
        acc.y = (acc.y + bv.y - mv.y) * sy + bev.y;
        acc.z = (acc.z + bv.z - mv.z) * sz + bev.z;
        acc.w = (acc.w + bv.w - mv.w) * sw + bev.w;
        acc.x = 1.f / (1.f + __expf(-acc.x));
        acc.y = 1.f / (1.f + __expf(-acc.y));
        acc.z = 1.f / (1.f + __expf(-acc.z));
        acc.w = 1.f / (1.f + __expf(-acc.w));
    }
    __half2 h0 = __floats2half2_rn(acc.x, acc.y);
    __half2 h1 = __floats2half2_rn(acc.z, acc.w);
    uint2 o;
    o.x = *(uint32_t*)&h0;
    o.y = *(uint32_t*)&h1;
    ((uint2*)dst)[node * du + cw] = o;
    PDL_TRIGGER();
}

// ---------------- fp16 mma.sync GEMM (m16n8k16), double-buffered cp.async ----------------
__device__ __forceinline__ void mma_f16(float* c, const uint32_t* a, const uint32_t* b) {
    asm volatile(
        "mma.sync.aligned.m16n8k16.row.col.f32.f16.f16.f32 "
        "{%0,%1,%2,%3}, {%4,%5,%6,%7}, {%8,%9}, {%0,%1,%2,%3};"
        : "+f"(c[0]), "+f"(c[1]), "+f"(c[2]), "+f"(c[3])
        : "r"(a[0]), "r"(a[1]), "r"(a[2]), "r"(a[3]), "r"(b[0]), "r"(b[1]));
}
__device__ __forceinline__ void cpa16(uint32_t smaddr, const void* g, int srcbytes) {
    asm volatile("cp.async.ca.shared.global [%0], [%1], 16, %2;"
                 :: "r"(smaddr), "l"(g), "r"(srcbytes) : "memory");
}
#define CP_COMMIT() asm volatile("cp.async.commit_group;" ::: "memory")
__device__ __forceinline__ uint32_t smem_u32(const void* p) {
    uint32_t a;
    asm("{ .reg .u64 t; cvta.to.shared.u64 t, %1; cvt.u32.u64 %0, t; }" : "=r"(a) : "l"(p));
    return a;
}

// tile: 128 rows x 32 halves, row stride 40 halves (20 words) -> conflict-free frags
#define TW 2560  // words per tile buffer

// EP: 0 raw, 1 sigmoid(BN(c+bias)), 2 sigmoid(c+bias); OUTH: 1 fp16 out, 0 fp32 out
template <int EP, int OUTH>
__global__ void __launch_bounds__(256, 2) k_tgemm(
    const __half* __restrict__ A, const __half* __restrict__ Bt, void* __restrict__ Cv,
    int M, int K, int Nc,
    const float* __restrict__ bias, const float* __restrict__ gm,
    const float* __restrict__ bt, const float* __restrict__ mn,
    const float* __restrict__ vr) {
    PDL_WAIT();
    __shared__ uint32_t sm[4 * TW];  // A0, A1, B0, B1
    uint32_t sb = smem_u32(sm);
    int t = threadIdx.x;
    int wid = t >> 5, lane = t & 31;
    int warp_m = wid & 1, warp_n = wid >> 1;  // 2 x 4 warps -> 128 x 128
    int m0 = blockIdx.x * 128, n0 = blockIdx.y * 128;
    int g4 = lane >> 2, l4 = lane & 3;

    float acc[4][4][4];
#pragma unroll
    for (int a = 0; a < 4; a++)
#pragma unroll
        for (int b = 0; b < 4; b++)
#pragma unroll
            for (int c = 0; c < 4; c++) acc[a][b][c] = 0.f;

    int fr[2], fq[2];
#pragma unroll
    for (int i = 0; i < 2; i++) {
        int f = t + 256 * i;
        fr[i] = f >> 2;        // row
        fq[i] = f & 3;         // 16B chunk within row (8 halves)
    }

    int nch = K >> 5;
    {
        uint32_t a_s = sb, b_s = sb + 2 * TW * 4;
#pragma unroll
        for (int i = 0; i < 2; i++) {
            int grow = m0 + fr[i];
            const __half* srcA = A + (long)(grow < M ? grow : 0) * K + fq[i] * 8;
            cpa16(a_s + (fr[i] * 20 + fq[i] * 4) * 4, srcA, grow < M ? 16 : 0);
            const __half* srcB = Bt + (long)(n0 + fr[i]) * K + fq[i] * 8;
            cpa16(b_s + (fr[i] * 20 + fq[i] * 4) * 4, srcB, 16);
        }
        CP_COMMIT();
    }

    for (int kc = 0; kc < nch; kc++) {
        if (kc + 1 < nch) {
            int buf = (kc + 1) & 1;
            int k0 = (kc + 1) << 5;
            uint32_t a_s = sb + buf * TW * 4;
            uint32_t b_s = sb + (2 * TW + buf * TW) * 4;
#pragma unroll
            for (int i = 0; i < 2; i++) {
                int grow = m0 + fr[i];
                const __half* srcA = A + (long)(grow < M ? grow : 0) * K + k0 + fq[i] * 8;
                cpa16(a_s + (fr[i] * 20 + fq[i] * 4) * 4, srcA, grow < M ? 16 : 0);
                const __half* srcB = Bt + (long)(n0 + fr[i]) * K + k0 + fq[i] * 8;
                cpa16(b_s + (fr[i] * 20 + fq[i] * 4) * 4, srcB, 16);
            }
            CP_COMMIT();
            asm volatile("cp.async.wait_group 1;" ::: "memory");
        } else {
            asm volatile("cp.async.wait_group 0;" ::: "memory");
        }
        __syncthreads();

        const uint32_t* Ab = sm + (kc & 1) * TW;
        const uint32_t* Bb = sm + 2 * TW + (kc & 1) * TW;
#pragma unroll
        for (int ks = 0; ks < 2; ks++) {
            int kk = ks * 8;  // word offset (16 halves)
            uint32_t af[4][4], bf[4][2];
#pragma unroll
            for (int mt = 0; mt < 4; mt++) {
                int mr = warp_m * 64 + mt * 16 + g4;
                const uint32_t* p = &Ab[mr * 20 + kk + l4];
                af[mt][0] = p[0];
                af[mt][1] = p[8 * 20];
                af[mt][2] = p[4];
                af[mt][3] = p[8 * 20 + 4];
            }
#pragma unroll
            for (int nt = 0; nt < 4; nt++) {
                int nr = warp_n * 32 + nt * 8 + g4;
                const uint32_t* p = &Bb[nr * 20 + kk + l4];
                bf[nt][0] = p[0];
                bf[nt][1] = p[4];
            }
#pragma unroll
            for (int mt = 0; mt < 4; mt++)
#pragma unroll
                for (int nt = 0; nt < 4; nt++) mma_f16(acc[mt][nt], af[mt], bf[nt]);
        }
        __syncthreads();
    }

    // epilogue
#pragma unroll
    for (int mt = 0; mt < 4; mt++) {
        int r = m0 + warp_m * 64 + mt * 16 + g4;
#pragma unroll
        for (int nt = 0; nt < 4; nt++) {
            int j0 = n0 + warp_n * 32 + nt * 8 + l4 * 2;
            float s0 = 1.f, o0 = 0.f, s1 = 1.f, o1 = 0.f;
            if (EP == 1) {
                s0 = gm[j0] * rsqrtf(vr[j0] + 1e-3f);
                o0 = (bias[j0] - mn[j0]) * s0 + bt[j0];
                s1 = gm[j0 + 1] * rsqrtf(vr[j0 + 1] + 1e-3f);
                o1 = (bias[j0 + 1] - mn[j0 + 1]) * s1 + bt[j0 + 1];
            } else if (EP == 2) {
                o0 = bias[j0];
                o1 = bias[j0 + 1];
            }
#pragma unroll
            for (int h = 0; h < 2; h++) {
                int rr = r + h * 8;
                if (rr >= M) continue;
                float v0 = acc[mt][nt][h * 2 + 0];
                float v1 = acc[mt][nt][h * 2 + 1];
                if (EP != 0) {
                    v0 = v0 * s0 + o0;
                    v1 = v1 * s1 + o1;
                    v0 = 1.f / (1.f + __expf(-v0));
                    v1 = 1.f / (1.f + __expf(-v1));
                }
                if (OUTH) {
                    __half2 hv = __floats2half2_rn(v0, v1);
                    *(__half2*)((__half*)Cv + (long)rr * Nc + j0) = hv;
                } else {
                    *(float2*)((float*)Cv + (long)rr * Nc + j0) = make_float2(v0, v1);
                }
            }
        }
    }
    PDL_TRIGGER();
}

// ---------------- Z = h^T h (fp32 for accuracy) ----------------
__global__ void __launch_bounds__(256) k_hth(const float* __restrict__ h, int M) {
    PDL_WAIT();
    __shared__ float sh[32][128];
    int t = threadIdx.x;
    int tx = t & 15, ty = t >> 4;
    int i0 = ty * 8, j0 = tx * 8;
    float acc[8][8];
#pragma unroll
    for (int a = 0; a < 8; a++)
#pragma unroll
        for (int b = 0; b < 8; b++) acc[a][b] = 0.f;

    int rpb = (M + gridDim.x - 1) / gridDim.x;
    int r0 = blockIdx.x * rpb;
    int r1 = min(M, r0 + rpb);
    for (int rb = r0; rb < r1; rb += 32) {
        int nrows = min(32, r1 - rb);
        for (int i = t; i < nrows * 32; i += 256) {
            int rr = i >> 5, c4 = i & 31;
            ((float4*)&sh[rr][0])[c4] = ((const float4*)(h + (long)(rb + rr) * 128))[c4];
        }
        __syncthreads();
        for (int r = 0; r < nrows; r++) {
            float4 a0 = *(const float4*)&sh[r][i0];
            float4 a1 = *(const float4*)&sh[r][i0 + 4];
            float4 b0 = *(const float4*)&sh[r][j0];
            float4 b1 = *(const float4*)&sh[r][j0 + 4];
            float ra[8] = {a0.x, a0.y, a0.z, a0.w, a1.x, a1.y, a1.z, a1.w};
            float rbv[8] = {b0.x, b0.y, b0.z, b0.w, b1.x, b1.y, b1.z, b1.w};
#pragma unroll
            for (int a = 0; a < 8; a++)
#pragma unroll
                for (int b = 0; b < 8; b++) acc[a][b] += ra[a] * rbv[b];
        }
        __syncthreads();
    }
#pragma unroll
    for (int a = 0; a < 8; a++)
#pragma unroll
        for (int b = 0; b < 8; b++)
            atomicAdd(&g_Z[(i0 + a) * 128 + j0 + b], acc[a][b]);
    PDL_TRIGGER();
}

// final output + cleanup for next graph replay (deg/cnt re-zeroed here;
// k_setup's atomics next call rely on it; first call uses static zero-init)
__global__ void k_final(float* __restrict__ out) {
    PDL_WAIT();
    int i = blockIdx.x * blockDim.x + threadIdx.x;
    if (i < 128 * 128) {
        int r = i >> 7, c = i & 127;
        out[i] = (r == c) ? 0.f : 0.5f * (g_Z[r * 128 + c] + g_Z[c * 128 + r]);
    }
    if (i < Nn) {
        g_deg[i] = 0.f;
        g_cnt[i] = 0;
    }
}

// ---------------- launch ----------------
extern "C" void kernel_launch(void* const* d_in, const int* in_sizes, int n_in,
                              void* d_out, int out_size) {
    const float* x = (const float*)d_in[0];
    const int* ei = (const int*)d_in[1];
    const float* ea = (const float*)d_in[2];
    const float *W[5], *bb[5];
    for (int i = 0; i < 5; i++) {
        W[i] = (const float*)d_in[3 + 2 * i];
        bb[i] = (const float*)d_in[4 + 2 * i];
    }
    const float *g[4], *be[4], *mn[4], *vr[4];
    for (int i = 0; i < 4; i++) {
        g[i] = (const float*)d_in[13 + 4 * i];
        be[i] = (const float*)d_in[14 + 4 * i];
        mn[i] = (const float*)d_in[15 + 4 * i];
        vr[i] = (const float*)d_in[16 + 4 * i];
    }
    const int* row = ei;
    const int* col = ei + Ee;

    float *A, *Bf, *WT;
    cudaGetSymbolAddress((void**)&A, g_bufA);
    cudaGetSymbolAddress((void**)&Bf, g_bufB);
    cudaGetSymbolAddress((void**)&WT, g_wT);
    __half* Ah = (__half*)A;
    __half* Bh = (__half*)Bf;
    __half* WTh = (__half*)WT;
    __half* Wt1 = WTh + 0;       // 256x128
    __half* Wt2 = WTh + 32768;   // 512x256
    __half* Wt3 = WTh + 163840;  // 256x512
    __half* Wt4 = WTh + 294912;  // 128x256
    __half* Wt5 = WTh + 327680;  // 128x128

    const int TB = 256;
    const float* nf = nullptr;

    // PDL launch attribute (used for every launch after the first)
    cudaLaunchAttribute pdlAttr;
    pdlAttr.id = cudaLaunchAttributeProgrammaticStreamSerialization;
    pdlAttr.val.programmaticStreamSerializationAllowed = 1;
    auto mkcfg = [&](dim3 grid, dim3 block) {
        cudaLaunchConfig_t cfg{};
        cfg.gridDim = grid;
        cfg.blockDim = block;
        cfg.dynamicSmemBytes = 0;
        cfg.stream = 0;
        cfg.attrs = &pdlAttr;
        cfg.numAttrs = 1;
        return cfg;
    };

    // ---- fused setup (plain launch) + CSR build (PDL chain from here on) ----
    k_setup<<<(1500448 + TB - 1) / TB, TB>>>(x, W[0], W[1], W[2], W[3], W[4], col, ea, WTh, Bh);
    {
        cudaLaunchConfig_t c1 = mkcfg(dim3(1), dim3(1024));
        cudaLaunchKernelEx(&c1, k_scan);
    }
    {
        cudaLaunchConfig_t c2 = mkcfg(dim3((Ee + TB - 1) / TB), dim3(TB));
        cudaLaunchKernelEx(&c2, k_fill, row, col, ea);
    }

    int w1 = Nn, w2 = Nn * 2;
    dim3 gb1((w1 * 32 + TB - 1) / TB), gb2((w2 * 32 + TB - 1) / TB);
    dim3 t157_1(157, 1), t157_2(157, 2), t157_4(157, 4), tb(TB);

    // L1: agg16(x16: Bh -> Ah, 128); fp16 GEMM(128->256)+BN+sig -> Bh
    {
        cudaLaunchConfig_t c = mkcfg(gb1, tb);
        cudaLaunchKernelEx(&c, k_agg16<0>, (const __half*)Bh, (__half*)Ah, 0, w1, nf, nf, nf, nf, nf);
    }
    {
        cudaLaunchConfig_t c = mkcfg(t157_2, tb);
        cudaLaunchKernelEx(&c, k_tgemm<1, 1>, (const __half*)Ah, (const __half*)Wt1, (void*)Bh,
                           Nn, 128, 256, bb[0], g[0], be[0], mn[0], vr[0]);
    }

    // L2: agg16(Bh -> Ah, 256); GEMM(256->512)+BN+sig -> Bh
    {
        cudaLaunchConfig_t c = mkcfg(gb2, tb);
        cudaLaunchKernelEx(&c, k_agg16<0>, (const __half*)Bh, (__half*)Ah, 1, w2, nf, nf, nf, nf, nf);
    }
    {
        cudaLaunchConfig_t c = mkcfg(t157_4, tb);
        cudaLaunchKernelEx(&c, k_tgemm<1, 1>, (const __half*)Ah, (const __half*)Wt2, (void*)Bh,
                           Nn, 256, 512, bb[1], g[1], be[1], mn[1], vr[1]);
    }

    // L3: GEMM(512->256) raw -> Ah; agg16+bias+BN+sig (Ah -> Bh, 256)
    {
        cudaLaunchConfig_t c = mkcfg(t157_2, tb);
        cudaLaunchKernelEx(&c, k_tgemm<0, 1>, (const __half*)Bh, (const __half*)Wt3, (void*)Ah,
                           Nn, 512, 256, nf, nf, nf, nf, nf);
    }
    {
        cudaLaunchConfig_t c = mkcfg(gb2, tb);
        cudaLaunchKernelEx(&c, k_agg16<1>, (const __half*)Ah, (__half*)Bh, 1, w2,
                           bb[2], g[2], be[2], mn[2], vr[2]);
    }

    // L4: GEMM(256->128) raw -> Ah; agg16+bias+BN+sig (Ah -> Bh, 128)
    {
        cudaLaunchConfig_t c = mkcfg(t157_1, tb);
        cudaLaunchKernelEx(&c, k_tgemm<0, 1>, (const __half*)Bh, (const __half*)Wt4, (void*)Ah,
                           Nn, 256, 128, nf, nf, nf, nf, nf);
    }
    {
        cudaLaunchConfig_t c = mkcfg(gb1, tb);
        cudaLaunchKernelEx(&c, k_agg16<1>, (const __half*)Ah, (__half*)Bh, 0, w1,
                           bb[3], g[3], be[3], mn[3], vr[3]);
    }

    // L5: agg16(Bh -> Ah, 128); GEMM(128->128)+bias+sig -> Bf fp32
    {
        cudaLaunchConfig_t c = mkcfg(gb1, tb);
        cudaLaunchKernelEx(&c, k_agg16<0>, (const __half*)Bh, (__half*)Ah, 0, w1, nf, nf, nf, nf, nf);
    }
    {
        cudaLaunchConfig_t c = mkcfg(t157_1, tb);
        cudaLaunchKernelEx(&c, k_tgemm<2, 0>, (const __half*)Ah, (const __half*)Wt5, (void*)Bf,
                           Nn, 128, 128, bb[4], nf, nf, nf, nf);
    }

    // final: Z = h^T h (fp32); symmetrize + zero diagonal; cleanup deg/cnt
    {
        cudaLaunchConfig_t c = mkcfg(dim3(157), tb);
        cudaLaunchKernelEx(&c, k_hth, (const float*)Bf, (int)Nn);
    }
    {
        cudaLaunchConfig_t c = mkcfg(dim3((Nn + TB - 1) / TB), tb);
        cudaLaunchKernelEx(&c, k_final, (float*)d_out);
    }
}

// round 17
// speedup vs baseline: 1.7299x; 1.1670x over previous
#include <cuda_runtime.h>
#include <cuda_fp16.h>
#include <cstdint>
#include <math.h>

#define Nn 20000
#define Ee 500000

// PDL: dependent-launch wait/trigger (sm_90+)
#define PDL_WAIT() asm volatile("griddepcontrol.wait;" ::: "memory")
#define PDL_TRIGGER() asm volatile("griddepcontrol.launch_dependents;" ::: "memory")

// ---------------- scratch (device globals; no allocation) ----------------
__device__ float g_deg[Nn];
__device__ int   g_cnt[Nn];
__device__ float g_dinv[Nn];
__device__ int   g_off[Nn + 1];
__device__ int   g_pos[Nn];
__device__ uint2 g_csr[Ee];      // interleaved (row, half2(w,w) bits)
__device__ float g_bufA[Nn * 512];
__device__ float g_bufB[Nn * 512];
__device__ float g_wT[344064];   // holds 344064 halves (transposed fp16 weights)
__device__ float g_Z[128 * 128];

// ---------------- fused setup: x cast, W transpose (coalesced writes), deg/cnt, Z zero ----------------
__global__ void k_setup(const float* __restrict__ x,
                        const float* __restrict__ W1, const float* __restrict__ W2,
                        const float* __restrict__ W3, const float* __restrict__ W4,
                        const float* __restrict__ W5,
                        const int* __restrict__ col, const float* __restrict__ ew,
                        __half* __restrict__ WTh, __half* __restrict__ xh) {
    int i = blockIdx.x * blockDim.x + threadIdx.x;
    if (i < 640000) {  // Nn*32 float4 units: cast x -> fp16
        float4 v = ((const float4*)x)[i];
        __half2 h0 = __floats2half2_rn(v.x, v.y);
        __half2 h1 = __floats2half2_rn(v.z, v.w);
        uint2 o;
        o.x = *(uint32_t*)&h0;
        o.y = *(uint32_t*)&h1;
        ((uint2*)xh)[i] = o;
    } else if (i < 984064) {  // Wt[N,K] fp16, output-indexed (coalesced writes)
        int j = i - 640000;
        if (j < 32768) {                       // L1: K=128, N=256
            int n = j >> 7, k = j & 127;
            WTh[j] = __float2half_rn(W1[k * 256 + n]);
        } else if (j < 163840) {               // L2: K=256, N=512
            int q = j - 32768;
            int n = q >> 8, k = q & 255;
            WTh[j] = __float2half_rn(W2[k * 512 + n]);
        } else if (j < 294912) {               // L3: K=512, N=256
            int q = j - 163840;
            int n = q >> 9, k = q & 511;
            WTh[j] = __float2half_rn(W3[k * 256 + n]);
        } else if (j < 327680) {               // L4: K=256, N=128
            int q = j - 294912;
            int n = q >> 8, k = q & 255;
            WTh[j] = __float2half_rn(W4[k * 128 + n]);
        } else {                               // L5: K=128, N=128
            int q = j - 327680;
            int n = q >> 7, k = q & 127;
            WTh[j] = __float2half_rn(W5[k * 128 + n]);
        }
    } else if (i < 1484064) {  // degree + count atomics (deg/cnt pre-zeroed by cleanup)
        int j = i - 984064;
        int c = col[j];
        atomicAdd(&g_deg[c], ew[j]);
        atomicAdd(&g_cnt[c], 1);
    } else if (i < 1500448) {  // zero Z (written only by k_hth, much later)
        g_Z[i - 1484064] = 0.f;
    }
    PDL_TRIGGER();
}

// scan of g_cnt -> g_off/g_pos, plus dinv (merged; 1 block, 1024 threads)
__global__ void __launch_bounds__(1024) k_scan() {
    PDL_WAIT();
    __shared__ int wsum[32];
    int t = threadIdx.x;
    const int C = 20;
    int base = t * C;
    int cnt[C];
    int s = 0;
#pragma unroll
    for (int i = 0; i < C; i++) {
        int idx = base + i;
        int c = 0;
        if (idx < Nn) {
            c = g_cnt[idx];
            g_dinv[idx] = rsqrtf(g_deg[idx] + 1.0f);
        }
        cnt[i] = c;
        s += c;
    }
    int lane = t & 31, w = t >> 5;
    int v = s;
#pragma unroll
    for (int o = 1; o < 32; o <<= 1) {
        int u = __shfl_up_sync(0xFFFFFFFF, v, o);
        if (lane >= o) v += u;
    }
    if (lane == 31) wsum[w] = v;
    __syncthreads();
    if (w == 0) {
        int x = wsum[lane];
#pragma unroll
        for (int o = 1; o < 32; o <<= 1) {
            int u = __shfl_up_sync(0xFFFFFFFF, x, o);
            if (lane >= o) x += u;
        }
        wsum[lane] = x;
    }
    __syncthreads();
    int run = v - s + (w > 0 ? wsum[w - 1] : 0);
#pragma unroll
    for (int i = 0; i < C; i++) {
        int idx = base + i;
        if (idx < Nn) {
            g_off[idx] = run;
            g_pos[idx] = run;
            run += cnt[i];
        }
    }
    if (t == 1023) g_off[Nn] = run;
    PDL_TRIGGER();
}

__global__ void k_fill(const int* __restrict__ row, const int* __restrict__ col,
                       const float* __restrict__ w) {
    PDL_WAIT();
    int i = blockIdx.x * blockDim.x + threadIdx.x;
    if (i < Ee) {
        int r = row[i], c = col[i];
        float nw = g_dinv[r] * w[i] * g_dinv[c];
        int p = atomicAdd(&g_pos[c], 1);
        __half2 wh = __floats2half2_rn(nw, nw);
        uint2 pr;
        pr.x = (uint32_t)r;
        pr.y = *(uint32_t*)&wh;
        g_csr[p] = pr;
    }
    PDL_TRIGGER();
}

// ---------------- atomic-free aggregation, fp16 HFMA2 inner loop (R12 proven) ----------------
#define HACC_EDGE(mm, vv)                                             \
    {                                                                 \
        __half2 w_ = *(__half2*)&(mm).y;                              \
        a0 = __hfma2(w_, *(__half2*)&(vv).x, a0);                     \
        a1 = __hfma2(w_, *(__half2*)&(vv).y, a1);                     \
    }
#define HFLUSH()                                                      \
    {                                                                 \
        float2 f0_ = __half22float2(a0);                              \
        float2 f1_ = __half22float2(a1);                              \
        acc.x += f0_.x; acc.y += f0_.y;                               \
        acc.z += f1_.x; acc.w += f1_.y;                               \
    }

// MODE 0: raw agg; MODE 1: agg + bias + BN + sigmoid
template <int MODE>
__global__ void __launch_bounds__(256) k_agg16(
    const __half* __restrict__ src, __half* __restrict__ dst,
    int nchl, int total_w,
    const float* __restrict__ b, const float* __restrict__ gm,
    const float* __restrict__ be, const float* __restrict__ mn,
    const float* __restrict__ vr) {
    PDL_WAIT();
    int wid = (blockIdx.x * 256 + threadIdx.x) >> 5;
    int lane = threadIdx.x & 31;
    if (wid >= total_w) return;
    int node = wid >> nchl;
    int chunk = wid & ((1 << nchl) - 1);
    int du = 32 << nchl;            // uint2 (4-half) units per row
    int cw = chunk * 32 + lane;
    const uint2* s2 = (const uint2*)src;
    const uint2* cp = g_csr;
    const __half2 hz = __floats2half2_rn(0.f, 0.f);

    float s0 = g_dinv[node];
    s0 *= s0;
    uint2 sv = s2[node * du + cw];
    float2 p0 = __half22float2(*(__half2*)&sv.x);
    float2 p1 = __half22float2(*(__half2*)&sv.y);
    float4 acc = make_float4(s0 * p0.x, s0 * p0.y, s0 * p1.x, s0 * p1.y);

    int e = g_off[node];
    int e1 = g_off[node + 1];
    for (; e + 8 <= e1; e += 8) {
        uint2 m[8], v[8];
#pragma unroll
        for (int j = 0; j < 8; j++) m[j] = cp[e + j];
#pragma unroll
        for (int j = 0; j < 8; j++) v[j] = s2[m[j].x * du + cw];
        __half2 a0 = hz, a1 = hz;
#pragma unroll
        for (int j = 0; j < 8; j++) HACC_EDGE(m[j], v[j]);
        HFLUSH();
    }
    if (e < e1) {
        uint2 m[8], v[8];
#pragma unroll
        for (int j = 0; j < 8; j++) {
            int idx = e + j;
            uint2 mm = make_uint2(0u, 0u);
            if (idx < e1) mm = cp[idx];
            m[j] = mm;
        }
#pragma unroll
        for (int j = 0; j < 8; j++) v[j] = s2[m[j].x * du + cw];
        __half2 a0 = hz, a1 = hz;
#pragma unroll
        for (int j = 0; j < 8; j++) HACC_EDGE(m[j], v[j]);
        HFLUSH();
    }

    if (MODE == 1) {
        float4 bv = ((const float4*)b)[cw];
        float4 gv = ((const float4*)gm)[cw];
        float4 bev = ((const float4*)be)[cw];
        float4 mv = ((const float4*)mn)[cw];
        float4 vv = ((const float4*)vr)[cw];
        float sx = gv.x * rsqrtf(vv.x + 1e-3f);
        float sy = gv.y * rsqrtf(vv.y + 1e-3f);
        float sz = gv.z * rsqrtf(vv.z + 1e-3f);
        float sw = gv.w * rsqrtf(vv.w + 1e-3f);
        acc.x = (acc.x + bv.x - mv.x) * sx + bev.x;
        acc.y = (acc.y + bv.y - mv.y) * sy + bev.y;
        acc.z = (acc.z + bv.z - mv.z) * sz + bev.z;
        acc.w = (acc.w + bv.w - mv.w) * sw + bev.w;
        acc.x = 1.f / (1.f + __expf(-acc.x));
        acc.y = 1.f / (1.f + __expf(-acc.y));
        acc.z = 1.f / (1.f + __expf(-acc.z));
        acc.w = 1.f / (1.f + __expf(-acc.w));
    }
    __half2 h0 = __floats2half2_rn(acc.x, acc.y);
    __half2 h1 = __floats2half2_rn(acc.z, acc.w);
    uint2 o;
    o.x = *(uint32_t*)&h0;
    o.y = *(uint32_t*)&h1;
    ((uint2*)dst)[node * du + cw] = o;
    PDL_TRIGGER();
}

// ---------------- fp16 mma.sync GEMM (m16n8k16), double-buffered cp.async ----------------
__device__ __forceinline__ void mma_f16(float* c, const uint32_t* a, const uint32_t* b) {
    asm volatile(
        "mma.sync.aligned.m16n8k16.row.col.f32.f16.f16.f32 "
        "{%0,%1,%2,%3}, {%4,%5,%6,%7}, {%8,%9}, {%0,%1,%2,%3};"
        : "+f"(c[0]), "+f"(c[1]), "+f"(c[2]), "+f"(c[3])
        : "r"(a[0]), "r"(a[1]), "r"(a[2]), "r"(a[3]), "r"(b[0]), "r"(b[1]));
}
__device__ __forceinline__ void cpa16(uint32_t smaddr, const void* g, int srcbytes) {
    asm volatile("cp.async.ca.shared.global [%0], [%1], 16, %2;"
                 :: "r"(smaddr), "l"(g), "r"(srcbytes) : "memory");
}
#define CP_COMMIT() asm volatile("cp.async.commit_group;" ::: "memory")
__device__ __forceinline__ uint32_t smem_u32(const void* p) {
    uint32_t a;
    asm("{ .reg .u64 t; cvta.to.shared.u64 t, %1; cvt.u32.u64 %0, t; }" : "=r"(a) : "l"(p));
    return a;
}

// tile: 128 rows x 32 halves, row stride 40 halves (20 words) -> conflict-free frags
#define TW 2560  // words per tile buffer

// EP: 0 raw, 1 sigmoid(BN(c+bias)), 2 sigmoid(c+bias); OUTH: 1 fp16 out, 0 fp32 out
template <int EP, int OUTH>
__global__ void __launch_bounds__(256, 2) k_tgemm(
    const __half* __restrict__ A, const __half* __restrict__ Bt, void* __restrict__ Cv,
    int M, int K, int Nc,
    const float* __restrict__ bias, const float* __restrict__ gm,
    const float* __restrict__ bt, const float* __restrict__ mn,
    const float* __restrict__ vr) {
    PDL_WAIT();
    __shared__ uint32_t sm[4 * TW];  // A0, A1, B0, B1
    uint32_t sb = smem_u32(sm);
    int t = threadIdx.x;
    int wid = t >> 5, lane = t & 31;
    int warp_m = wid & 1, warp_n = wid >> 1;  // 2 x 4 warps -> 128 x 128
    int m0 = blockIdx.x * 128, n0 = blockIdx.y * 128;
    int g4 = lane >> 2, l4 = lane & 3;

    float acc[4][4][4];
#pragma unroll
    for (int a = 0; a < 4; a++)
#pragma unroll
        for (int b = 0; b < 4; b++)
#pragma unroll
            for (int c = 0; c < 4; c++) acc[a][b][c] = 0.f;

    int fr[2], fq[2];
#pragma unroll
    for (int i = 0; i < 2; i++) {
        int f = t + 256 * i;
        fr[i] = f >> 2;
        fq[i] = f & 3;
    }

    int nch = K >> 5;
    {
        uint32_t a_s = sb, b_s = sb + 2 * TW * 4;
#pragma unroll
        for (int i = 0; i < 2; i++) {
            int grow = m0 + fr[i];
            const __half* srcA = A + (long)(grow < M ? grow : 0) * K + fq[i] * 8;
            cpa16(a_s + (fr[i] * 20 + fq[i] * 4) * 4, srcA, grow < M ? 16 : 0);
            const __half* srcB = Bt + (long)(n0 + fr[i]) * K + fq[i] * 8;
            cpa16(b_s + (fr[i] * 20 + fq[i] * 4) * 4, srcB, 16);
        }
        CP_COMMIT();
    }

    for (int kc = 0; kc < nch; kc++) {
        if (kc + 1 < nch) {
            int buf = (kc + 1) & 1;
            int k0 = (kc + 1) << 5;
            uint32_t a_s = sb + buf * TW * 4;
            uint32_t b_s = sb + (2 * TW + buf * TW) * 4;
#pragma unroll
            for (int i = 0; i < 2; i++) {
                int grow = m0 + fr[i];
                const __half* srcA = A + (long)(grow < M ? grow : 0) * K + k0 + fq[i] * 8;
                cpa16(a_s + (fr[i] * 20 + fq[i] * 4) * 4, srcA, grow < M ? 16 : 0);
                const __half* srcB = Bt + (long)(n0 + fr[i]) * K + k0 + fq[i] * 8;
                cpa16(b_s + (fr[i] * 20 + fq[i] * 4) * 4, srcB, 16);
            }
            CP_COMMIT();
            asm volatile("cp.async.wait_group 1;" ::: "memory");
        } else {
            asm volatile("cp.async.wait_group 0;" ::: "memory");
        }
        __syncthreads();

        const uint32_t* Ab = sm + (kc & 1) * TW;
        const uint32_t* Bb = sm + 2 * TW + (kc & 1) * TW;
#pragma unroll
        for (int ks = 0; ks < 2; ks++) {
            int kk = ks * 8;
            uint32_t af[4][4], bf[4][2];
#pragma unroll
            for (int mt = 0; mt < 4; mt++) {
                int mr = warp_m * 64 + mt * 16 + g4;
                const uint32_t* p = &Ab[mr * 20 + kk + l4];
                af[mt][0] = p[0];
                af[mt][1] = p[8 * 20];
                af[mt][2] = p[4];
                af[mt][3] = p[8 * 20 + 4];
            }
#pragma unroll
            for (int nt = 0; nt < 4; nt++) {
                int nr = warp_n * 32 + nt * 8 + g4;
                const uint32_t* p = &Bb[nr * 20 + kk + l4];
                bf[nt][0] = p[0];
                bf[nt][1] = p[4];
            }
#pragma unroll
            for (int mt = 0; mt < 4; mt++)
#pragma unroll
                for (int nt = 0; nt < 4; nt++) mma_f16(acc[mt][nt], af[mt], bf[nt]);
        }
        __syncthreads();
    }

    // epilogue
#pragma unroll
    for (int mt = 0; mt < 4; mt++) {
        int r = m0 + warp_m * 64 + mt * 16 + g4;
#pragma unroll
        for (int nt = 0; nt < 4; nt++) {
            int j0 = n0 + warp_n * 32 + nt * 8 + l4 * 2;
            float s0 = 1.f, o0 = 0.f, s1 = 1.f, o1 = 0.f;
            if (EP == 1) {
                s0 = gm[j0] * rsqrtf(vr[j0] + 1e-3f);
                o0 = (bias[j0] - mn[j0]) * s0 + bt[j0];
                s1 = gm[j0 + 1] * rsqrtf(vr[j0 + 1] + 1e-3f);
                o1 = (bias[j0 + 1] - mn[j0 + 1]) * s1 + bt[j0 + 1];
            } else if (EP == 2) {
                o0 = bias[j0];
                o1 = bias[j0 + 1];
            }
#pragma unroll
            for (int h = 0; h < 2; h++) {
                int rr = r + h * 8;
                if (rr >= M) continue;
                float v0 = acc[mt][nt][h * 2 + 0];
                float v1 = acc[mt][nt][h * 2 + 1];
                if (EP != 0) {
                    v0 = v0 * s0 + o0;
                    v1 = v1 * s1 + o1;
                    v0 = 1.f / (1.f + __expf(-v0));
                    v1 = 1.f / (1.f + __expf(-v1));
                }
                if (OUTH) {
                    __half2 hv = __floats2half2_rn(v0, v1);
                    *(__half2*)((__half*)Cv + (long)rr * Nc + j0) = hv;
                } else {
                    *(float2*)((float*)Cv + (long)rr * Nc + j0) = make_float2(v0, v1);
                }
            }
        }
    }
    PDL_TRIGGER();
}

// ---------------- Z = h^T h via fp16 tensor cores (h fp16, fp32 accumulate) ----------------
__global__ void __launch_bounds__(256) k_hth(const __half* __restrict__ h, int M) {
    PDL_WAIT();
    __shared__ __half sht[128 * 18];  // transposed tile: [col i][k], stride 18 halves
    int t = threadIdx.x;
    int wid = t >> 5, lane = t & 31;
    int warp_m = wid & 1, warp_n = wid >> 1;  // 2 x 4 warps -> 128 x 128
    int g4 = lane >> 2, l4 = lane & 3;

    float acc[4][4][4];
#pragma unroll
    for (int a = 0; a < 4; a++)
#pragma unroll
        for (int b = 0; b < 4; b++)
#pragma unroll
            for (int c = 0; c < 4; c++) acc[a][b][c] = 0.f;

    int rpb = (M + gridDim.x - 1) / gridDim.x;
    rpb = (rpb + 15) & ~15;  // multiple of 16
    int r0 = blockIdx.x * rpb;
    int r1 = min(M, r0 + rpb);
    int sk = t >> 4, sib = (t & 15) * 8;  // stage coords: 16 rows x 16 col-chunks

    for (int rb = r0; rb < r1; rb += 16) {
        // stage 16 rows transposed (rows beyond M padded with zeros)
        {
            int grow = rb + sk;
            uint4 v = make_uint4(0u, 0u, 0u, 0u);
            if (grow < M) v = *(const uint4*)(h + (long)grow * 128 + sib);
            const __half* hv = (const __half*)&v;
#pragma unroll
            for (int j = 0; j < 8; j++) sht[(sib + j) * 18 + sk] = hv[j];
        }
        __syncthreads();
        // one k=16 mma step over the 128x128 output tile
        uint32_t af[4][4], bf[4][2];
#pragma unroll
        for (int mt = 0; mt < 4; mt++) {
            int i = warp_m * 64 + mt * 16 + g4;
            af[mt][0] = *(const uint32_t*)&sht[i * 18 + 2 * l4];
            af[mt][1] = *(const uint32_t*)&sht[(i + 8) * 18 + 2 * l4];
            af[mt][2] = *(const uint32_t*)&sht[i * 18 + 2 * l4 + 8];
            af[mt][3] = *(const uint32_t*)&sht[(i + 8) * 18 + 2 * l4 + 8];
        }
#pragma unroll
        for (int nt = 0; nt < 4; nt++) {
            int n = warp_n * 32 + nt * 8 + g4;
            bf[nt][0] = *(const uint32_t*)&sht[n * 18 + 2 * l4];
            bf[nt][1] = *(const uint32_t*)&sht[n * 18 + 2 * l4 + 8];
        }
#pragma unroll
        for (int mt = 0; mt < 4; mt++)
#pragma unroll
            for (int nt = 0; nt < 4; nt++) mma_f16(acc[mt][nt], af[mt], bf[nt]);
        __syncthreads();
    }

    // accumulate into g_Z
#pragma unroll
    for (int mt = 0; mt < 4; mt++) {
        int r = warp_m * 64 + mt * 16 + g4;
#pragma unroll
        for (int nt = 0; nt < 4; nt++) {
            int j0 = warp_n * 32 + nt * 8 + l4 * 2;
#pragma unroll
            for (int hh = 0; hh < 2; hh++) {
                int rr = r + hh * 8;
                atomicAdd(&g_Z[rr * 128 + j0], acc[mt][nt][hh * 2]);
                atomicAdd(&g_Z[rr * 128 + j0 + 1], acc[mt][nt][hh * 2 + 1]);
            }
        }
    }
    PDL_TRIGGER();
}

// final output + cleanup for next graph replay
__global__ void k_final(float* __restrict__ out) {
    PDL_WAIT();
    int i = blockIdx.x * blockDim.x + threadIdx.x;
    if (i < 128 * 128) {
        int r = i >> 7, c = i & 127;
        out[i] = (r == c) ? 0.f : 0.5f * (g_Z[r * 128 + c] + g_Z[c * 128 + r]);
    }
    if (i < Nn) {
        g_deg[i] = 0.f;
        g_cnt[i] = 0;
    }
}

// ---------------- launch ----------------
extern "C" void kernel_launch(void* const* d_in, const int* in_sizes, int n_in,
                              void* d_out, int out_size) {
    const float* x = (const float*)d_in[0];
    const int* ei = (const int*)d_in[1];
    const float* ea = (const float*)d_in[2];
    const float *W[5], *bb[5];
    for (int i = 0; i < 5; i++) {
        W[i] = (const float*)d_in[3 + 2 * i];
        bb[i] = (const float*)d_in[4 + 2 * i];
    }
    const float *g[4], *be[4], *mn[4], *vr[4];
    for (int i = 0; i < 4; i++) {
        g[i] = (const float*)d_in[13 + 4 * i];
        be[i] = (const float*)d_in[14 + 4 * i];
        mn[i] = (const float*)d_in[15 + 4 * i];
        vr[i] = (const float*)d_in[16 + 4 * i];
    }
    const int* row = ei;
    const int* col = ei + Ee;

    float *A, *Bf, *WT;
    cudaGetSymbolAddress((void**)&A, g_bufA);
    cudaGetSymbolAddress((void**)&Bf, g_bufB);
    cudaGetSymbolAddress((void**)&WT, g_wT);
    __half* Ah = (__half*)A;
    __half* Bh = (__half*)Bf;
    __half* WTh = (__half*)WT;
    __half* Wt1 = WTh + 0;       // 256x128
    __half* Wt2 = WTh + 32768;   // 512x256
    __half* Wt3 = WTh + 163840;  // 256x512
    __half* Wt4 = WTh + 294912;  // 128x256
    __half* Wt5 = WTh + 327680;  // 128x128

    const int TB = 256;
    const float* nf = nullptr;

    cudaLaunchAttribute pdlAttr;
    pdlAttr.id = cudaLaunchAttributeProgrammaticStreamSerialization;
    pdlAttr.val.programmaticStreamSerializationAllowed = 1;
    auto mkcfg = [&](dim3 grid, dim3 block) {
        cudaLaunchConfig_t cfg{};
        cfg.gridDim = grid;
        cfg.blockDim = block;
        cfg.dynamicSmemBytes = 0;
        cfg.stream = 0;
        cfg.attrs = &pdlAttr;
        cfg.numAttrs = 1;
        return cfg;
    };

    // ---- fused setup (plain launch) + CSR build (PDL chain) ----
    k_setup<<<(1500448 + TB - 1) / TB, TB>>>(x, W[0], W[1], W[2], W[3], W[4], col, ea, WTh, Bh);
    {
        cudaLaunchConfig_t c1 = mkcfg(dim3(1), dim3(1024));
        cudaLaunchKernelEx(&c1, k_scan);
    }
    {
        cudaLaunchConfig_t c2 = mkcfg(dim3((Ee + TB - 1) / TB), dim3(TB));
        cudaLaunchKernelEx(&c2, k_fill, row, col, ea);
    }

    int w1 = Nn, w2 = Nn * 2;
    dim3 gb1((w1 * 32 + TB - 1) / TB), gb2((w2 * 32 + TB - 1) / TB);
    dim3 t157_1(157, 1), t157_2(157, 2), t157_4(157, 4), tb(TB);

    // L1: agg16(x16: Bh -> Ah, 128); fp16 GEMM(128->256)+BN+sig -> Bh
    {
        cudaLaunchConfig_t c = mkcfg(gb1, tb);
        cudaLaunchKernelEx(&c, k_agg16<0>, (const __half*)Bh, (__half*)Ah, 0, w1, nf, nf, nf, nf, nf);
    }
    {
        cudaLaunchConfig_t c = mkcfg(t157_2, tb);
        cudaLaunchKernelEx(&c, k_tgemm<1, 1>, (const __half*)Ah, (const __half*)Wt1, (void*)Bh,
                           Nn, 128, 256, bb[0], g[0], be[0], mn[0], vr[0]);
    }

    // L2: agg16(Bh -> Ah, 256); GEMM(256->512)+BN+sig -> Bh
    {
        cudaLaunchConfig_t c = mkcfg(gb2, tb);
        cudaLaunchKernelEx(&c, k_agg16<0>, (const __half*)Bh, (__half*)Ah, 1, w2, nf, nf, nf, nf, nf);
    }
    {
        cudaLaunchConfig_t c = mkcfg(t157_4, tb);
        cudaLaunchKernelEx(&c, k_tgemm<1, 1>, (const __half*)Ah, (const __half*)Wt2, (void*)Bh,
                           Nn, 256, 512, bb[1], g[1], be[1], mn[1], vr[1]);
    }

    // L3: GEMM(512->256) raw -> Ah; agg16+bias+BN+sig (Ah -> Bh, 256)
    {
        cudaLaunchConfig_t c = mkcfg(t157_2, tb);
        cudaLaunchKernelEx(&c, k_tgemm<0, 1>, (const __half*)Bh, (const __half*)Wt3, (void*)Ah,
                           Nn, 512, 256, nf, nf, nf, nf, nf);
    }
    {
        cudaLaunchConfig_t c = mkcfg(gb2, tb);
        cudaLaunchKernelEx(&c, k_agg16<1>, (const __half*)Ah, (__half*)Bh, 1, w2,
                           bb[2], g[2], be[2], mn[2], vr[2]);
    }

    // L4: GEMM(256->128) raw -> Ah; agg16+bias+BN+sig (Ah -> Bh, 128)
    {
        cudaLaunchConfig_t c = mkcfg(t157_1, tb);
        cudaLaunchKernelEx(&c, k_tgemm<0, 1>, (const __half*)Bh, (const __half*)Wt4, (void*)Ah,
                           Nn, 256, 128, nf, nf, nf, nf, nf);
    }
    {
        cudaLaunchConfig_t c = mkcfg(gb1, tb);
        cudaLaunchKernelEx(&c, k_agg16<1>, (const __half*)Ah, (__half*)Bh, 0, w1,
                           bb[3], g[3], be[3], mn[3], vr[3]);
    }

    // L5: agg16(Bh -> Ah, 128); GEMM(128->128)+bias+sig -> h5 fp16 in Bh
    {
        cudaLaunchConfig_t c = mkcfg(gb1, tb);
        cudaLaunchKernelEx(&c, k_agg16<0>, (const __half*)Bh, (__half*)Ah, 0, w1, nf, nf, nf, nf, nf);
    }
    {
        cudaLaunchConfig_t c = mkcfg(t157_1, tb);
        cudaLaunchKernelEx(&c, k_tgemm<2, 1>, (const __half*)Ah, (const __half*)Wt5, (void*)Bh,
                           Nn, 128, 128, bb[4], nf, nf, nf, nf);
    }

    // final: Z = h^T h (fp16 tensor cores, fp32 acc); symmetrize; cleanup
    {
        cudaLaunchConfig_t c = mkcfg(dim3(157), tb);
        cudaLaunchKernelEx(&c, k_hth, (const __half*)Bh, (int)Nn);
    }
    {
        cudaLaunchConfig_t c = mkcfg(dim3((Nn + TB - 1) / TB), tb);
        cudaLaunchKernelEx(&c, k_final, (float*)d_out);
    }
}